// round 1
// baseline (speedup 1.0000x reference)
#include <cuda_runtime.h>
#include <cuda_bf16.h>
#include <math.h>

// ---------------------------------------------------------------------------
// RPN: conv3x3(2048->2048, 28x28, pad1) + bias + relu
//      -> 1x1 heads (reg 36ch, cls 9ch) + sigmoid
//      -> static valid-anchor gather (4850) masked by cls > 0.9
// Round 1: fp32-exact implicit GEMM using packed f32x2 FFMA (FFMA2).
// ---------------------------------------------------------------------------

#define KTOT  18432        // 2048 * 9
#define NPIX  784          // 28*28
#define CBM   64
#define CBN   64
#define CBK   32
#define NCHUNK (KTOT / CBK)   // 576

typedef unsigned long long u64;

__device__ float g_h[2048 * NPIX];      // conv output (post relu)
__device__ float g_head[45 * NPIX];     // 36 reg + 9 cls, post sigmoid
__device__ int   g_vpos[7056];          // anchor -> output slot (or -1)

__device__ __forceinline__ u64 pk2(float lo, float hi) {
    u64 r; asm("mov.b64 %0, {%1, %2};" : "=l"(r) : "f"(lo), "f"(hi)); return r;
}
__device__ __forceinline__ u64 ffma2(u64 a, u64 b, u64 c) {
    u64 d; asm("fma.rn.f32x2 %0, %1, %2, %3;" : "=l"(d) : "l"(a), "l"(b), "l"(c)); return d;
}
__device__ __forceinline__ float2 up2(u64 v) {
    float2 f; asm("mov.b64 {%0, %1}, %2;" : "=f"(f.x), "=f"(f.y) : "l"(v)); return f;
}

// ---------------------------------------------------------------------------
// Conv as implicit GEMM:  out[oc, p] = sum_k W[oc, k] * im2col(k, p)
//   k = ic*9 + ky*3 + kx  (exactly the contiguous layout of conv_w)
// Block tile 64x64, K-chunk 32, 64 threads (8x8), 8x8 outputs per thread.
// Double-buffered smem with register prefetch; f32x2 packed FMAs.
// ---------------------------------------------------------------------------
__global__ __launch_bounds__(64) void conv_kernel(
    const float* __restrict__ X,      // [2048, 28, 28]
    const float* __restrict__ W,      // [2048, 18432]
    const float* __restrict__ Bb)     // [2048]
{
    __shared__ __align__(16) float As[2][CBK][CBM];      // [k][m]
    __shared__ __align__(16) float Bs[2][CBK][CBN + 2];  // [k][n], pad 66 (even)

    const int tid = threadIdx.x;
    const int tx = tid & 7;           // N-dim thread coord
    const int ty = tid >> 3;          // M-dim thread coord
    const int n0 = blockIdx.x * CBN;  // pixel base
    const int m0 = blockIdx.y * CBM;  // out-channel base

    // ---- fetch assignments ----
    // A: thread owns row (m0 + tid), loads 32 k-values (8 float4)
    const float* wrow = W + (size_t)(m0 + tid) * KTOT;
    // B: thread owns k = tid&31, n-half = (tid>>5)*32, loads 32 pixels
    const int bk = tid & 31;
    const int bn = (tid >> 5) * 32;

    float4 pa[8];
    float  pb[32];

    u64 acc[8][4];
    #pragma unroll
    for (int m = 0; m < 8; m++)
        #pragma unroll
        for (int j = 0; j < 4; j++) acc[m][j] = 0ull;

    // ---- prologue: fetch chunk 0, stash ----
    {
        const float4* src = (const float4*)(wrow);
        #pragma unroll
        for (int i = 0; i < 8; i++) pa[i] = src[i];
        const int kg = bk;
        const int ic = kg / 9, t = kg % 9;
        const int ky = t / 3 - 1, kx = t % 3 - 1;
        const float* xp = X + ic * NPIX;
        #pragma unroll
        for (int j = 0; j < 32; j++) {
            int p = n0 + bn + j;
            float v = 0.f;
            if (p < NPIX) {
                int y = p / 28 + ky, x = p % 28 + kx;
                if ((unsigned)y < 28u && (unsigned)x < 28u) v = __ldg(&xp[y * 28 + x]);
            }
            pb[j] = v;
        }
        #pragma unroll
        for (int i = 0; i < 8; i++) {
            As[0][4 * i + 0][tid] = pa[i].x;
            As[0][4 * i + 1][tid] = pa[i].y;
            As[0][4 * i + 2][tid] = pa[i].z;
            As[0][4 * i + 3][tid] = pa[i].w;
        }
        #pragma unroll
        for (int j = 0; j < 32; j++) Bs[0][bk][bn + j] = pb[j];
    }
    __syncthreads();

    for (int c = 0; c < NCHUNK; ++c) {
        const int cur = c & 1;
        const bool more = (c + 1 < NCHUNK);

        // ---- prefetch next chunk into registers ----
        if (more) {
            const float4* src = (const float4*)(wrow + (c + 1) * CBK);
            #pragma unroll
            for (int i = 0; i < 8; i++) pa[i] = src[i];
            const int kg = (c + 1) * CBK + bk;
            const int ic = kg / 9, t = kg % 9;
            const int ky = t / 3 - 1, kx = t % 3 - 1;
            const float* xp = X + ic * NPIX;
            #pragma unroll
            for (int j = 0; j < 32; j++) {
                int p = n0 + bn + j;
                float v = 0.f;
                if (p < NPIX) {
                    int y = p / 28 + ky, x = p % 28 + kx;
                    if ((unsigned)y < 28u && (unsigned)x < 28u) v = __ldg(&xp[y * 28 + x]);
                }
                pb[j] = v;
            }
        }

        // ---- compute on current smem buffer ----
        #pragma unroll 8
        for (int kk = 0; kk < CBK; kk++) {
            float4 a0 = *(const float4*)&As[cur][kk][ty * 8];
            float4 a1 = *(const float4*)&As[cur][kk][ty * 8 + 4];
            const u64* bp = (const u64*)&Bs[cur][kk][tx * 8];
            u64 b0 = bp[0], b1 = bp[1], b2 = bp[2], b3 = bp[3];
            u64 ad[8];
            ad[0] = pk2(a0.x, a0.x); ad[1] = pk2(a0.y, a0.y);
            ad[2] = pk2(a0.z, a0.z); ad[3] = pk2(a0.w, a0.w);
            ad[4] = pk2(a1.x, a1.x); ad[5] = pk2(a1.y, a1.y);
            ad[6] = pk2(a1.z, a1.z); ad[7] = pk2(a1.w, a1.w);
            #pragma unroll
            for (int m = 0; m < 8; m++) {
                acc[m][0] = ffma2(ad[m], b0, acc[m][0]);
                acc[m][1] = ffma2(ad[m], b1, acc[m][1]);
                acc[m][2] = ffma2(ad[m], b2, acc[m][2]);
                acc[m][3] = ffma2(ad[m], b3, acc[m][3]);
            }
        }

        // ---- stash prefetched regs into other buffer ----
        if (more) {
            const int nxt = 1 - cur;
            #pragma unroll
            for (int i = 0; i < 8; i++) {
                As[nxt][4 * i + 0][tid] = pa[i].x;
                As[nxt][4 * i + 1][tid] = pa[i].y;
                As[nxt][4 * i + 2][tid] = pa[i].z;
                As[nxt][4 * i + 3][tid] = pa[i].w;
            }
            #pragma unroll
            for (int j = 0; j < 32; j++) Bs[nxt][bk][bn + j] = pb[j];
        }
        __syncthreads();
    }

    // ---- epilogue: bias + relu -> g_h ----
    #pragma unroll
    for (int m = 0; m < 8; m++) {
        const int oc = m0 + ty * 8 + m;
        const float bias = Bb[oc];
        #pragma unroll
        for (int j = 0; j < 4; j++) {
            float2 v = up2(acc[m][j]);
            int p = n0 + tx * 8 + 2 * j;
            if (p < NPIX)     g_h[oc * NPIX + p]     = fmaxf(v.x + bias, 0.f);
            if (p + 1 < NPIX) g_h[oc * NPIX + p + 1] = fmaxf(v.y + bias, 0.f);
        }
    }
}

// ---------------------------------------------------------------------------
// Heads: 45 x 784 logits over 2048 channels, + sigmoid.
// One block per pixel, 128 threads reduce over channels.
// ---------------------------------------------------------------------------
__global__ void heads_kernel(
    const float* __restrict__ reg_w, const float* __restrict__ reg_b,
    const float* __restrict__ cls_w, const float* __restrict__ cls_b)
{
    const int p = blockIdx.x;
    const int tid = threadIdx.x;
    const int lane = tid & 31, warp = tid >> 5;

    float hv[16];
    #pragma unroll
    for (int i = 0; i < 16; i++) hv[i] = g_h[(tid + 128 * i) * NPIX + p];

    __shared__ float red[4];

    for (int o = 0; o < 45; o++) {
        const float* w = (o < 36) ? (reg_w + o * 2048) : (cls_w + (o - 36) * 2048);
        float s = 0.f;
        #pragma unroll
        for (int i = 0; i < 16; i++) s += hv[i] * __ldg(&w[tid + 128 * i]);
        #pragma unroll
        for (int off = 16; off > 0; off >>= 1) s += __shfl_xor_sync(0xffffffffu, s, off);
        if (lane == 0) red[warp] = s;
        __syncthreads();
        if (tid == 0) {
            float t = red[0] + red[1] + red[2] + red[3];
            t += (o < 36) ? reg_b[o] : cls_b[o - 36];
            g_head[o * NPIX + p] = 1.f / (1.f + expf(-t));
        }
        __syncthreads();
    }
}

// ---------------------------------------------------------------------------
// Valid-anchor geometry: exact fp64 replica of the numpy reference.
// anchor j (boxes ordering) = pixel*9 + a,  a = scale_idx*3 + ratio_idx
// ---------------------------------------------------------------------------
__device__ __forceinline__ bool anchor_valid(int j) {
    int a = j % 9, p = j / 9;
    int y = p / 28, x = p % 28;
    double scale = (a / 3 == 0) ? 64.0 : (a / 3 == 1) ? 128.0 : 256.0;
    double ratio = (a % 3 == 0) ? 0.5 : (a % 3 == 1) ? 1.0 : 2.0;
    double hh = scale / sqrt(ratio) / 448.0;
    double ww = scale * sqrt(ratio) / 448.0;
    double cy = ((double)y + 0.5) / 28.0;
    double cx = ((double)x + 0.5) / 28.0;
    double y1 = cy - hh / 2.0, x1 = cx - ww / 2.0;
    double y2 = cy + hh / 2.0, x2 = cx + ww / 2.0;
    return (y1 > 0.0) && (x1 > 0.0) && (y2 < 28.0) && (x2 < 28.0);
}

// One block, 1024 threads: count + block scan -> g_vpos
__global__ void scan_kernel() {
    __shared__ int s[1024];
    const int tid = threadIdx.x;
    const int base = tid * 7;
    int f[7];
    int cnt = 0;
    #pragma unroll
    for (int i = 0; i < 7; i++) {
        int j = base + i;
        f[i] = (j < 7056 && anchor_valid(j)) ? 1 : 0;
        cnt += f[i];
    }
    s[tid] = cnt;
    __syncthreads();
    for (int off = 1; off < 1024; off <<= 1) {
        int v = s[tid];
        int add = (tid >= off) ? s[tid - off] : 0;
        __syncthreads();
        s[tid] = v + add;
        __syncthreads();
    }
    int pos = s[tid] - cnt;   // exclusive prefix
    #pragma unroll
    for (int i = 0; i < 7; i++) {
        int j = base + i;
        if (j < 7056) {
            g_vpos[j] = f[i] ? pos : -1;
            pos += f[i];
        }
    }
}

// ---------------------------------------------------------------------------
// Gather: replicate reference's index semantics exactly.
// _VALID holds boxes-ordering indices j, applied to arrays in (a = j/784,
// p = j%784) layout (that's the reference's own view/permute behavior).
// ---------------------------------------------------------------------------
__global__ void gather_kernel(float* __restrict__ out) {
    int j = blockIdx.x * blockDim.x + threadIdx.x;
    if (j >= 7056) return;
    int slot = g_vpos[j];
    if (slot < 0) return;
    int a = j / NPIX, p = j % NPIX;
    float cls = g_head[(36 + a) * NPIX + p];
    float k = (cls > 0.9f) ? 1.f : 0.f;
    #pragma unroll
    for (int c = 0; c < 4; c++)
        out[slot * 4 + c] = g_head[(c * 9 + a) * NPIX + p] * k;
}

// ---------------------------------------------------------------------------
extern "C" void kernel_launch(void* const* d_in, const int* in_sizes, int n_in,
                              void* d_out, int out_size)
{
    const float* x      = (const float*)d_in[0];
    const float* conv_w = (const float*)d_in[1];
    const float* conv_b = (const float*)d_in[2];
    const float* reg_w  = (const float*)d_in[3];
    const float* reg_b  = (const float*)d_in[4];
    const float* cls_w  = (const float*)d_in[5];
    const float* cls_b  = (const float*)d_in[6];
    float* out = (float*)d_out;

    dim3 gc((NPIX + CBN - 1) / CBN, 2048 / CBM);   // (13, 32)
    conv_kernel<<<gc, 64>>>(x, conv_w, conv_b);
    heads_kernel<<<NPIX, 128>>>(reg_w, reg_b, cls_w, cls_b);
    scan_kernel<<<1, 1024>>>();
    gather_kernel<<<28, 256>>>(out);
}

// round 4
// speedup vs baseline: 3.5222x; 3.5222x over previous
#include <cuda_runtime.h>
#include <cuda_fp16.h>
#include <math.h>
#include <stdint.h>

// ---------------------------------------------------------------------------
// RPN round 4: split-fp16 (2-split, 3-product) implicit GEMM on mma.sync.
// Fix vs R3: k-step offset must be XORed into the swizzled fragment address
// (SWZ is an XOR transform; SWZ(base+kd) == SWZ(base)^kd for kd in bits 5..6).
// ---------------------------------------------------------------------------

#define KTOT  18432            // 2048*9
#define NPIX  784
#define KC    64               // K elems per stage
#define NCH   (KTOT / KC)      // 288
#define TM    128
#define TN    112              // 784 = 7*112
#define NSTG  3
#define A_BYTES (TM * 128)     // 16384
#define B_BYTES (TN * 128)     // 14336
#define STG_SZ  (2 * A_BYTES + 2 * B_BYTES)   // 61440
#define OFF_AH  0
#define OFF_AL  A_BYTES
#define OFF_BH  (2 * A_BYTES)
#define OFF_BL  (2 * A_BYTES + B_BYTES)
#define CONV_SMEM (NSTG * STG_SZ + 1024)

__device__ __half g_whi[2048 * KTOT];
__device__ __half g_wlo[2048 * KTOT];
__device__ __half g_bhi[NPIX * KTOT];
__device__ __half g_blo[NPIX * KTOT];
__device__ float g_h[2048 * NPIX];
__device__ float g_head[45 * NPIX];
__device__ int   g_vpos[7056];

#define SWZ(o) ((uint32_t)(o) ^ ((((uint32_t)(o)) >> 3) & 0x70u))

__device__ __forceinline__ uint32_t smem_u32(const void* p) {
    uint32_t a;
    asm("{ .reg .u64 t; cvta.to.shared.u64 t, %1; cvt.u32.u64 %0, t; }"
        : "=r"(a) : "l"(p));
    return a;
}
__device__ __forceinline__ void cpa16(uint32_t dst, const void* src) {
    asm volatile("cp.async.cg.shared.global [%0], [%1], 16;"
                 :: "r"(dst), "l"(src) : "memory");
}
__device__ __forceinline__ void ldsm4(uint32_t* r, uint32_t addr) {
    asm volatile("ldmatrix.sync.aligned.m8n8.x4.shared.b16 {%0,%1,%2,%3}, [%4];"
                 : "=r"(r[0]), "=r"(r[1]), "=r"(r[2]), "=r"(r[3]) : "r"(addr));
}
__device__ __forceinline__ void ldsm2(uint32_t* r, uint32_t addr) {
    asm volatile("ldmatrix.sync.aligned.m8n8.x2.shared.b16 {%0,%1}, [%2];"
                 : "=r"(r[0]), "=r"(r[1]) : "r"(addr));
}
__device__ __forceinline__ void mma16816(float* d, const uint32_t* a, const uint32_t* b) {
    asm volatile(
        "mma.sync.aligned.m16n8k16.row.col.f32.f16.f16.f32 "
        "{%0,%1,%2,%3}, {%4,%5,%6,%7}, {%8,%9}, {%0,%1,%2,%3};"
        : "+f"(d[0]), "+f"(d[1]), "+f"(d[2]), "+f"(d[3])
        : "r"(a[0]), "r"(a[1]), "r"(a[2]), "r"(a[3]), "r"(b[0]), "r"(b[1]));
}

// ------------------------------ split W ------------------------------------
__global__ __launch_bounds__(256) void split_w_kernel(const float* __restrict__ W) {
    int i = blockIdx.x * blockDim.x + threadIdx.x;
    const int n4 = (2048 * KTOT) / 4;
    if (i >= n4) return;
    float4 v = ((const float4*)W)[i];
    __half h[4], l[4];
    h[0] = __float2half_rn(v.x); h[1] = __float2half_rn(v.y);
    h[2] = __float2half_rn(v.z); h[3] = __float2half_rn(v.w);
    l[0] = __float2half_rn(v.x - __half2float(h[0]));
    l[1] = __float2half_rn(v.y - __half2float(h[1]));
    l[2] = __float2half_rn(v.z - __half2float(h[2]));
    l[3] = __float2half_rn(v.w - __half2float(h[3]));
    ((uint2*)g_whi)[i] = *(uint2*)h;
    ((uint2*)g_wlo)[i] = *(uint2*)l;
}

// --------------------------- split im2col of X -----------------------------
__global__ __launch_bounds__(256) void im2col_kernel(const float* __restrict__ X) {
    int t = blockIdx.x * blockDim.x + threadIdx.x;
    const int nt = NPIX * (KTOT / 8);
    if (t >= nt) return;
    int p = t / (KTOT / 8);
    int kq = (t - p * (KTOT / 8)) * 8;
    int y = p / 28, x = p - (p / 28) * 28;
    __half hi[8], lo[8];
    #pragma unroll
    for (int j = 0; j < 8; j++) {
        int k = kq + j;
        int ic = k / 9, o = k - ic * 9;
        int ky = o / 3 - 1, kx = o - (o / 3) * 3 - 1;
        int yy = y + ky, xx = x + kx;
        float v = 0.f;
        if ((unsigned)yy < 28u && (unsigned)xx < 28u)
            v = __ldg(&X[ic * NPIX + yy * 28 + xx]);
        hi[j] = __float2half_rn(v);
        lo[j] = __float2half_rn(v - __half2float(hi[j]));
    }
    size_t off = (size_t)p * KTOT + kq;
    ((uint4*)(g_bhi + off))[0] = *(uint4*)hi;
    ((uint4*)(g_blo + off))[0] = *(uint4*)lo;
}

// ------------------------------ conv GEMM ----------------------------------
__global__ __launch_bounds__(256, 1) void conv_mma_kernel(const float* __restrict__ CB) {
    extern __shared__ char smraw[];
    uintptr_t basep = ((uintptr_t)smraw + 1023) & ~(uintptr_t)1023;
    const uint32_t smb = smem_u32((void*)basep);

    const int tid  = threadIdx.x;
    const int wid  = tid >> 5;
    const int lane = tid & 31;
    const int wm   = (wid & 3) * 32;
    const int wn   = (wid >> 2) * 56;
    const int m0   = blockIdx.y * TM;
    const int n0   = blockIdx.x * TN;

    uint32_t aoff[2], boff[7];
    {
        int arow = wm + (lane & 15);
        int acol = (lane >> 4) * 16;
        #pragma unroll
        for (int mt = 0; mt < 2; mt++)
            aoff[mt] = SWZ((arow + mt * 16) * 128 + acol);
        int bi = lane & 15;
        int brow = wn + (bi & 7);
        int bcol = ((bi >> 3) & 1) * 16;
        #pragma unroll
        for (int nt = 0; nt < 7; nt++)
            boff[nt] = SWZ((brow + nt * 8) * 128 + bcol);
    }

    float acc[2][7][4];
    #pragma unroll
    for (int mt = 0; mt < 2; mt++)
        #pragma unroll
        for (int nt = 0; nt < 7; nt++)
            #pragma unroll
            for (int i = 0; i < 4; i++) acc[mt][nt][i] = 0.f;

    auto load_stage = [&](int it) {
        const int stg = it % NSTG;
        const uint32_t sb = smb + stg * STG_SZ;
        const int kc = it * KC;
        #pragma unroll
        for (int q = tid; q < 1024; q += 256) {
            int r = q >> 3, c = q & 7;
            uint32_t so = SWZ(r * 128 + c * 16);
            size_t go = (size_t)(m0 + r) * KTOT + kc + c * 8;
            cpa16(sb + OFF_AH + so, g_whi + go);
            cpa16(sb + OFF_AL + so, g_wlo + go);
        }
        #pragma unroll
        for (int q = tid; q < 896; q += 256) {
            int r = q >> 3, c = q & 7;
            uint32_t so = SWZ(r * 128 + c * 16);
            size_t go = (size_t)(n0 + r) * KTOT + kc + c * 8;
            cpa16(sb + OFF_BH + so, g_bhi + go);
            cpa16(sb + OFF_BL + so, g_blo + go);
        }
    };

    load_stage(0);
    asm volatile("cp.async.commit_group;" ::: "memory");
    load_stage(1);
    asm volatile("cp.async.commit_group;" ::: "memory");

    for (int c = 0; c < NCH; ++c) {
        asm volatile("cp.async.wait_group 1;" ::: "memory");
        __syncthreads();

        if (c + 2 < NCH) load_stage(c + 2);
        asm volatile("cp.async.commit_group;" ::: "memory");

        const uint32_t sb = smb + (c % NSTG) * STG_SZ;
        #pragma unroll
        for (int kk = 0; kk < 4; kk++) {
            const uint32_t kd = kk * 32;           // bytes; XOR into swizzled addr
            uint32_t ah[2][4], al[2][4], bh[7][2], bl[7][2];
            #pragma unroll
            for (int mt = 0; mt < 2; mt++) {
                ldsm4(ah[mt], sb + OFF_AH + (aoff[mt] ^ kd));
                ldsm4(al[mt], sb + OFF_AL + (aoff[mt] ^ kd));
            }
            #pragma unroll
            for (int nt = 0; nt < 7; nt++) {
                ldsm2(bh[nt], sb + OFF_BH + (boff[nt] ^ kd));
                ldsm2(bl[nt], sb + OFF_BL + (boff[nt] ^ kd));
            }
            #pragma unroll
            for (int mt = 0; mt < 2; mt++)
                #pragma unroll
                for (int nt = 0; nt < 7; nt++) {
                    mma16816(acc[mt][nt], ah[mt], bh[nt]);
                    mma16816(acc[mt][nt], ah[mt], bl[nt]);
                    mma16816(acc[mt][nt], al[mt], bh[nt]);
                }
        }
    }

    const int l4 = lane >> 2;
    const int l2 = (lane & 3) * 2;
    #pragma unroll
    for (int mt = 0; mt < 2; mt++) {
        int ocA = m0 + wm + mt * 16 + l4;
        int ocB = ocA + 8;
        float biasA = __ldg(&CB[ocA]);
        float biasB = __ldg(&CB[ocB]);
        #pragma unroll
        for (int nt = 0; nt < 7; nt++) {
            int p = n0 + wn + nt * 8 + l2;
            float2 vA, vB;
            vA.x = fmaxf(acc[mt][nt][0] + biasA, 0.f);
            vA.y = fmaxf(acc[mt][nt][1] + biasA, 0.f);
            vB.x = fmaxf(acc[mt][nt][2] + biasB, 0.f);
            vB.y = fmaxf(acc[mt][nt][3] + biasB, 0.f);
            *(float2*)(g_h + (size_t)ocA * NPIX + p) = vA;
            *(float2*)(g_h + (size_t)ocB * NPIX + p) = vB;
        }
    }
}

// ------------------------------- heads -------------------------------------
__global__ void heads_kernel(
    const float* __restrict__ reg_w, const float* __restrict__ reg_b,
    const float* __restrict__ cls_w, const float* __restrict__ cls_b)
{
    const int p = blockIdx.x;
    const int tid = threadIdx.x;
    const int lane = tid & 31, warp = tid >> 5;

    float hv[16];
    #pragma unroll
    for (int i = 0; i < 16; i++) hv[i] = g_h[(size_t)(tid + 128 * i) * NPIX + p];

    __shared__ float red[4];

    for (int o = 0; o < 45; o++) {
        const float* w = (o < 36) ? (reg_w + o * 2048) : (cls_w + (o - 36) * 2048);
        float s = 0.f;
        #pragma unroll
        for (int i = 0; i < 16; i++) s += hv[i] * __ldg(&w[tid + 128 * i]);
        #pragma unroll
        for (int off = 16; off > 0; off >>= 1) s += __shfl_xor_sync(0xffffffffu, s, off);
        if (lane == 0) red[warp] = s;
        __syncthreads();
        if (tid == 0) {
            float t = red[0] + red[1] + red[2] + red[3];
            t += (o < 36) ? reg_b[o] : cls_b[o - 36];
            g_head[o * NPIX + p] = 1.f / (1.f + expf(-t));
        }
        __syncthreads();
    }
}

// ------------------------- anchor validity + scan --------------------------
__device__ __forceinline__ bool anchor_valid(int j) {
    int a = j % 9, p = j / 9;
    int y = p / 28, x = p % 28;
    double scale = (a / 3 == 0) ? 64.0 : (a / 3 == 1) ? 128.0 : 256.0;
    double ratio = (a % 3 == 0) ? 0.5 : (a % 3 == 1) ? 1.0 : 2.0;
    double hh = scale / sqrt(ratio) / 448.0;
    double ww = scale * sqrt(ratio) / 448.0;
    double cy = ((double)y + 0.5) / 28.0;
    double cx = ((double)x + 0.5) / 28.0;
    double y1 = cy - hh / 2.0, x1 = cx - ww / 2.0;
    double y2 = cy + hh / 2.0, x2 = cx + ww / 2.0;
    return (y1 > 0.0) && (x1 > 0.0) && (y2 < 28.0) && (x2 < 28.0);
}

__global__ void scan_kernel() {
    __shared__ int s[1024];
    const int tid = threadIdx.x;
    const int base = tid * 7;
    int f[7];
    int cnt = 0;
    #pragma unroll
    for (int i = 0; i < 7; i++) {
        int j = base + i;
        f[i] = (j < 7056 && anchor_valid(j)) ? 1 : 0;
        cnt += f[i];
    }
    s[tid] = cnt;
    __syncthreads();
    for (int off = 1; off < 1024; off <<= 1) {
        int v = s[tid];
        int add = (tid >= off) ? s[tid - off] : 0;
        __syncthreads();
        s[tid] = v + add;
        __syncthreads();
    }
    int pos = s[tid] - cnt;
    #pragma unroll
    for (int i = 0; i < 7; i++) {
        int j = base + i;
        if (j < 7056) {
            g_vpos[j] = f[i] ? pos : -1;
            pos += f[i];
        }
    }
}

__global__ void gather_kernel(float* __restrict__ out) {
    int j = blockIdx.x * blockDim.x + threadIdx.x;
    if (j >= 7056) return;
    int slot = g_vpos[j];
    if (slot < 0) return;
    int a = j / NPIX, p = j % NPIX;
    float cls = g_head[(36 + a) * NPIX + p];
    float k = (cls > 0.9f) ? 1.f : 0.f;
    #pragma unroll
    for (int c = 0; c < 4; c++)
        out[slot * 4 + c] = g_head[(c * 9 + a) * NPIX + p] * k;
}

// ---------------------------------------------------------------------------
extern "C" void kernel_launch(void* const* d_in, const int* in_sizes, int n_in,
                              void* d_out, int out_size)
{
    const float* x      = (const float*)d_in[0];
    const float* conv_w = (const float*)d_in[1];
    const float* conv_b = (const float*)d_in[2];
    const float* reg_w  = (const float*)d_in[3];
    const float* reg_b  = (const float*)d_in[4];
    const float* cls_w  = (const float*)d_in[5];
    const float* cls_b  = (const float*)d_in[6];
    float* out = (float*)d_out;

    cudaFuncSetAttribute(conv_mma_kernel,
                         cudaFuncAttributeMaxDynamicSharedMemorySize, CONV_SMEM);

    split_w_kernel<<<(2048 * KTOT / 4 + 255) / 256, 256>>>(conv_w);
    im2col_kernel<<<(NPIX * (KTOT / 8) + 255) / 256, 256>>>(x);
    conv_mma_kernel<<<dim3(7, 16), 256, CONV_SMEM>>>(conv_b);
    heads_kernel<<<NPIX, 128>>>(reg_w, reg_b, cls_w, cls_b);
    scan_kernel<<<1, 1024>>>();
    gather_kernel<<<28, 256>>>(out);
}

// round 5
// speedup vs baseline: 3.6278x; 1.0300x over previous
#include <cuda_runtime.h>
#include <cuda_fp16.h>
#include <math.h>
#include <stdint.h>

// ---------------------------------------------------------------------------
// RPN round 5: split-fp16 implicit GEMM (3 HMMA products).
//  - conv grid 16x9 = 144 CTAs (TN=96, N padded to 864, zfill) for SM util
//  - B fragments via paired ldmatrix.x4
//  - heads: warp-per-pixel, sync-free
//  - scan+gather merged
// ---------------------------------------------------------------------------

#define KTOT  18432
#define NPIX  784
#define KC    64
#define NCH   (KTOT / KC)      // 288
#define TM    128
#define TN    96               // 9 blocks cover 864 (pad)
#define NSTG  3
#define A_BYTES (TM * 128)     // 16384
#define B_BYTES (TN * 128)     // 12288
#define STG_SZ  (2 * A_BYTES + 2 * B_BYTES)   // 57344
#define OFF_AH  0
#define OFF_AL  A_BYTES
#define OFF_BH  (2 * A_BYTES)
#define OFF_BL  (2 * A_BYTES + B_BYTES)
#define CONV_SMEM (NSTG * STG_SZ + 1024)

__device__ __half g_whi[2048 * KTOT];
__device__ __half g_wlo[2048 * KTOT];
__device__ __half g_bhi[NPIX * KTOT];
__device__ __half g_blo[NPIX * KTOT];
__device__ float g_h[2048 * NPIX];
__device__ float g_head[45 * NPIX];

#define SWZ(o) ((uint32_t)(o) ^ ((((uint32_t)(o)) >> 3) & 0x70u))

__device__ __forceinline__ uint32_t smem_u32(const void* p) {
    uint32_t a;
    asm("{ .reg .u64 t; cvta.to.shared.u64 t, %1; cvt.u32.u64 %0, t; }"
        : "=r"(a) : "l"(p));
    return a;
}
__device__ __forceinline__ void cpa16(uint32_t dst, const void* src) {
    asm volatile("cp.async.cg.shared.global [%0], [%1], 16;"
                 :: "r"(dst), "l"(src) : "memory");
}
__device__ __forceinline__ void cpa16z(uint32_t dst, const void* src, int sz) {
    asm volatile("cp.async.cg.shared.global [%0], [%1], 16, %2;"
                 :: "r"(dst), "l"(src), "r"(sz) : "memory");
}
__device__ __forceinline__ void ldsm4(uint32_t* r, uint32_t addr) {
    asm volatile("ldmatrix.sync.aligned.m8n8.x4.shared.b16 {%0,%1,%2,%3}, [%4];"
                 : "=r"(r[0]), "=r"(r[1]), "=r"(r[2]), "=r"(r[3]) : "r"(addr));
}
__device__ __forceinline__ void mma16816(float* d, const uint32_t* a, const uint32_t* b) {
    asm volatile(
        "mma.sync.aligned.m16n8k16.row.col.f32.f16.f16.f32 "
        "{%0,%1,%2,%3}, {%4,%5,%6,%7}, {%8,%9}, {%0,%1,%2,%3};"
        : "+f"(d[0]), "+f"(d[1]), "+f"(d[2]), "+f"(d[3])
        : "r"(a[0]), "r"(a[1]), "r"(a[2]), "r"(a[3]), "r"(b[0]), "r"(b[1]));
}

// ------------------------------ split W ------------------------------------
__global__ __launch_bounds__(256) void split_w_kernel(const float* __restrict__ W) {
    int i = blockIdx.x * blockDim.x + threadIdx.x;
    const int n4 = (2048 * KTOT) / 4;
    if (i >= n4) return;
    float4 v = ((const float4*)W)[i];
    __half h[4], l[4];
    h[0] = __float2half_rn(v.x); h[1] = __float2half_rn(v.y);
    h[2] = __float2half_rn(v.z); h[3] = __float2half_rn(v.w);
    l[0] = __float2half_rn(v.x - __half2float(h[0]));
    l[1] = __float2half_rn(v.y - __half2float(h[1]));
    l[2] = __float2half_rn(v.z - __half2float(h[2]));
    l[3] = __float2half_rn(v.w - __half2float(h[3]));
    ((uint2*)g_whi)[i] = *(uint2*)h;
    ((uint2*)g_wlo)[i] = *(uint2*)l;
}

// --------------------------- split im2col of X -----------------------------
__global__ __launch_bounds__(256) void im2col_kernel(const float* __restrict__ X) {
    int t = blockIdx.x * blockDim.x + threadIdx.x;
    const int nt = NPIX * (KTOT / 8);
    if (t >= nt) return;
    int p = t / (KTOT / 8);
    int kq = (t - p * (KTOT / 8)) * 8;
    int y = p / 28, x = p - (p / 28) * 28;
    __half hi[8], lo[8];
    #pragma unroll
    for (int j = 0; j < 8; j++) {
        int k = kq + j;
        int ic = k / 9, o = k - ic * 9;
        int ky = o / 3 - 1, kx = o - (o / 3) * 3 - 1;
        int yy = y + ky, xx = x + kx;
        float v = 0.f;
        if ((unsigned)yy < 28u && (unsigned)xx < 28u)
            v = __ldg(&X[ic * NPIX + yy * 28 + xx]);
        hi[j] = __float2half_rn(v);
        lo[j] = __float2half_rn(v - __half2float(hi[j]));
    }
    size_t off = (size_t)p * KTOT + kq;
    ((uint4*)(g_bhi + off))[0] = *(uint4*)hi;
    ((uint4*)(g_blo + off))[0] = *(uint4*)lo;
}

// ------------------------------ conv GEMM ----------------------------------
// CTA tile 128x96, 8 warps as 4M x 2N (warp tile 32x48)
__global__ __launch_bounds__(256, 1) void conv_mma_kernel(const float* __restrict__ CB) {
    extern __shared__ char smraw[];
    uintptr_t basep = ((uintptr_t)smraw + 1023) & ~(uintptr_t)1023;
    const uint32_t smb = smem_u32((void*)basep);

    const int tid  = threadIdx.x;
    const int wid  = tid >> 5;
    const int lane = tid & 31;
    const int wm   = (wid & 3) * 32;
    const int wn   = (wid >> 2) * 48;
    const int m0   = blockIdx.y * TM;
    const int n0   = blockIdx.x * TN;

    // A fragment offsets: 2 mt tiles (m16 each)
    uint32_t aoff[2];
    {
        int arow = wm + (lane & 15);
        int acol = (lane >> 4) * 16;
        #pragma unroll
        for (int mt = 0; mt < 2; mt++)
            aoff[mt] = SWZ((arow + mt * 16) * 128 + acol);
    }
    // B fragment offsets: 3 paired-x4 loads cover 6 n8 tiles
    uint32_t boff[3];
    {
        int brow = wn + ((lane >> 4) & 1) * 8 + (lane & 7);
        int bcol = ((lane >> 3) & 1) * 16;
        #pragma unroll
        for (int t = 0; t < 3; t++)
            boff[t] = SWZ((brow + t * 16) * 128 + bcol);
    }

    float acc[2][6][4];
    #pragma unroll
    for (int mt = 0; mt < 2; mt++)
        #pragma unroll
        for (int nt = 0; nt < 6; nt++)
            #pragma unroll
            for (int i = 0; i < 4; i++) acc[mt][nt][i] = 0.f;

    auto load_stage = [&](int it) {
        const int stg = it % NSTG;
        const uint32_t sb = smb + stg * STG_SZ;
        const int kc = it * KC;
        #pragma unroll
        for (int q = tid; q < 1024; q += 256) {           // A: 128 rows x 8
            int r = q >> 3, c = q & 7;
            uint32_t so = SWZ(r * 128 + c * 16);
            size_t go = (size_t)(m0 + r) * KTOT + kc + c * 8;
            cpa16(sb + OFF_AH + so, g_whi + go);
            cpa16(sb + OFF_AL + so, g_wlo + go);
        }
        #pragma unroll
        for (int q = tid; q < 768; q += 256) {            // B: 96 rows x 8
            int r = q >> 3, c = q & 7;
            uint32_t so = SWZ(r * 128 + c * 16);
            int valid = (n0 + r < NPIX) ? 16 : 0;
            size_t go = (size_t)min(n0 + r, NPIX - 1) * KTOT + kc + c * 8;
            cpa16z(sb + OFF_BH + so, g_bhi + go, valid);
            cpa16z(sb + OFF_BL + so, g_blo + go, valid);
        }
    };

    load_stage(0);
    asm volatile("cp.async.commit_group;" ::: "memory");
    load_stage(1);
    asm volatile("cp.async.commit_group;" ::: "memory");

    for (int c = 0; c < NCH; ++c) {
        asm volatile("cp.async.wait_group 1;" ::: "memory");
        __syncthreads();

        if (c + 2 < NCH) load_stage(c + 2);
        asm volatile("cp.async.commit_group;" ::: "memory");

        const uint32_t sb = smb + (c % NSTG) * STG_SZ;
        #pragma unroll
        for (int kk = 0; kk < 4; kk++) {
            const uint32_t kd = kk * 32;
            uint32_t ah[2][4], al[2][4], bh[6][2], bl[6][2];
            #pragma unroll
            for (int mt = 0; mt < 2; mt++) {
                ldsm4(ah[mt], sb + OFF_AH + (aoff[mt] ^ kd));
                ldsm4(al[mt], sb + OFF_AL + (aoff[mt] ^ kd));
            }
            #pragma unroll
            for (int t = 0; t < 3; t++) {
                uint32_t tmp[4];
                ldsm4(tmp, sb + OFF_BH + (boff[t] ^ kd));
                bh[2 * t][0] = tmp[0]; bh[2 * t][1] = tmp[1];
                bh[2 * t + 1][0] = tmp[2]; bh[2 * t + 1][1] = tmp[3];
                ldsm4(tmp, sb + OFF_BL + (boff[t] ^ kd));
                bl[2 * t][0] = tmp[0]; bl[2 * t][1] = tmp[1];
                bl[2 * t + 1][0] = tmp[2]; bl[2 * t + 1][1] = tmp[3];
            }
            #pragma unroll
            for (int mt = 0; mt < 2; mt++)
                #pragma unroll
                for (int nt = 0; nt < 6; nt++) {
                    mma16816(acc[mt][nt], ah[mt], bh[nt]);
                    mma16816(acc[mt][nt], ah[mt], bl[nt]);
                    mma16816(acc[mt][nt], al[mt], bh[nt]);
                }
        }
    }

    const int l4 = lane >> 2;
    const int l2 = (lane & 3) * 2;
    #pragma unroll
    for (int mt = 0; mt < 2; mt++) {
        int ocA = m0 + wm + mt * 16 + l4;
        int ocB = ocA + 8;
        float biasA = __ldg(&CB[ocA]);
        float biasB = __ldg(&CB[ocB]);
        #pragma unroll
        for (int nt = 0; nt < 6; nt++) {
            int p = n0 + wn + nt * 8 + l2;
            if (p < NPIX) {
                float2 vA, vB;
                vA.x = fmaxf(acc[mt][nt][0] + biasA, 0.f);
                vA.y = fmaxf(acc[mt][nt][1] + biasA, 0.f);
                vB.x = fmaxf(acc[mt][nt][2] + biasB, 0.f);
                vB.y = fmaxf(acc[mt][nt][3] + biasB, 0.f);
                *(float2*)(g_h + (size_t)ocA * NPIX + p) = vA;
                *(float2*)(g_h + (size_t)ocB * NPIX + p) = vB;
            }
        }
    }
}

// ------------------------------- heads -------------------------------------
// 98 blocks x 8 warps; warp w handles pixel blockIdx.x*8 + w. No block syncs.
__global__ __launch_bounds__(256) void heads_kernel(
    const float* __restrict__ reg_w, const float* __restrict__ reg_b,
    const float* __restrict__ cls_w, const float* __restrict__ cls_b)
{
    const int lane = threadIdx.x & 31;
    const int warp = threadIdx.x >> 5;
    const int p = blockIdx.x * 8 + warp;

    // lane owns channels lane*4 + t + 128*j  (t<4, j<16)
    float hv[16][4];
    #pragma unroll
    for (int j = 0; j < 16; j++) {
        int ch = lane * 4 + 128 * j;
        #pragma unroll
        for (int t = 0; t < 4; t++)
            hv[j][t] = g_h[(size_t)(ch + t) * NPIX + p];
    }

    #pragma unroll 1
    for (int o = 0; o < 45; o++) {
        const float* w = (o < 36) ? (reg_w + o * 2048) : (cls_w + (o - 36) * 2048);
        float s = 0.f;
        #pragma unroll
        for (int j = 0; j < 16; j++) {
            float4 wq = __ldg((const float4*)(w + lane * 4 + 128 * j));
            s += hv[j][0] * wq.x + hv[j][1] * wq.y + hv[j][2] * wq.z + hv[j][3] * wq.w;
        }
        #pragma unroll
        for (int off = 16; off > 0; off >>= 1) s += __shfl_xor_sync(0xffffffffu, s, off);
        if (lane == 0) {
            float b = (o < 36) ? __ldg(&reg_b[o]) : __ldg(&cls_b[o - 36]);
            float t = s + b;
            g_head[o * NPIX + p] = 1.f / (1.f + expf(-t));
        }
    }
}

// ------------------------- scan + gather (fused) ---------------------------
__device__ __forceinline__ bool anchor_valid(int j) {
    int a = j % 9, p = j / 9;
    int y = p / 28, x = p % 28;
    double scale = (a / 3 == 0) ? 64.0 : (a / 3 == 1) ? 128.0 : 256.0;
    double ratio = (a % 3 == 0) ? 0.5 : (a % 3 == 1) ? 1.0 : 2.0;
    double hh = scale / sqrt(ratio) / 448.0;
    double ww = scale * sqrt(ratio) / 448.0;
    double cy = ((double)y + 0.5) / 28.0;
    double cx = ((double)x + 0.5) / 28.0;
    double y1 = cy - hh / 2.0, x1 = cx - ww / 2.0;
    double y2 = cy + hh / 2.0, x2 = cx + ww / 2.0;
    return (y1 > 0.0) && (x1 > 0.0) && (y2 < 28.0) && (x2 < 28.0);
}

__global__ void scan_gather_kernel(float* __restrict__ out) {
    __shared__ int s[1024];
    const int tid = threadIdx.x;
    const int base = tid * 7;
    int f[7];
    int cnt = 0;
    #pragma unroll
    for (int i = 0; i < 7; i++) {
        int j = base + i;
        f[i] = (j < 7056 && anchor_valid(j)) ? 1 : 0;
        cnt += f[i];
    }
    s[tid] = cnt;
    __syncthreads();
    for (int off = 1; off < 1024; off <<= 1) {
        int v = s[tid];
        int add = (tid >= off) ? s[tid - off] : 0;
        __syncthreads();
        s[tid] = v + add;
        __syncthreads();
    }
    int pos = s[tid] - cnt;
    #pragma unroll
    for (int i = 0; i < 7; i++) {
        int j = base + i;
        if (j < 7056 && f[i]) {
            int a = j / NPIX, p = j % NPIX;
            float cls = g_head[(36 + a) * NPIX + p];
            float k = (cls > 0.9f) ? 1.f : 0.f;
            #pragma unroll
            for (int c = 0; c < 4; c++)
                out[pos * 4 + c] = g_head[(c * 9 + a) * NPIX + p] * k;
            pos++;
        }
    }
}

// ---------------------------------------------------------------------------
extern "C" void kernel_launch(void* const* d_in, const int* in_sizes, int n_in,
                              void* d_out, int out_size)
{
    const float* x      = (const float*)d_in[0];
    const float* conv_w = (const float*)d_in[1];
    const float* conv_b = (const float*)d_in[2];
    const float* reg_w  = (const float*)d_in[3];
    const float* reg_b  = (const float*)d_in[4];
    const float* cls_w  = (const float*)d_in[5];
    const float* cls_b  = (const float*)d_in[6];
    float* out = (float*)d_out;

    cudaFuncSetAttribute(conv_mma_kernel,
                         cudaFuncAttributeMaxDynamicSharedMemorySize, CONV_SMEM);

    split_w_kernel<<<(2048 * KTOT / 4 + 255) / 256, 256>>>(conv_w);
    im2col_kernel<<<(NPIX * (KTOT / 8) + 255) / 256, 256>>>(x);
    conv_mma_kernel<<<dim3(9, 16), 256, CONV_SMEM>>>(conv_b);
    heads_kernel<<<98, 256>>>(reg_w, reg_b, cls_w, cls_b);
    scan_gather_kernel<<<1, 1024>>>(out);
}

// round 6
// speedup vs baseline: 3.6697x; 1.0116x over previous
#include <cuda_runtime.h>
#include <cuda_fp16.h>
#include <math.h>
#include <stdint.h>

// ---------------------------------------------------------------------------
// RPN round 6: Winograd F(2x2,3x3) + split-fp16 (3-product) HMMA GEMMs.
//   conv3x3 -> 16 GEMMs M=2048 K=2048 N=196(pad 224), 1.97x less MMA work.
//   transforms in fp32; heads via transposed activations (coalesced).
// ---------------------------------------------------------------------------

#define NPIX  784
#define NT14  14               // 14x14 tiles
#define NTIL  196
#define NTP   224              // padded tiles (2 x 112)
#define KDIM  2048
#define KC    64
#define NCH   (KDIM / KC)      // 32
#define TM    128
#define TN    112
#define NSTG  3
#define A_BYTES (TM * 128)     // 16384
#define B_BYTES (TN * 128)     // 14336
#define STG_SZ  (2 * A_BYTES + 2 * B_BYTES)   // 61440
#define OFF_AH  0
#define OFF_AL  A_BYTES
#define OFF_BH  (2 * A_BYTES)
#define OFF_BL  (2 * A_BYTES + B_BYTES)
#define CONV_SMEM (NSTG * STG_SZ + 1024)

#define USTRIDE (2048 * 2048)          // per-position U elems
#define VSTRIDE (NTP * 2048)           // per-position V elems
#define MSTRIDE (2048 * NTP)           // per-position m elems

__device__ __half g_Uhi[16 * USTRIDE];
__device__ __half g_Ulo[16 * USTRIDE];
__device__ __half g_Vhi[16 * VSTRIDE];
__device__ __half g_Vlo[16 * VSTRIDE];
__device__ float  g_m[16 * MSTRIDE];
__device__ float  g_h[2048 * NPIX];
__device__ float  g_ht[NPIX * 2048];
__device__ float  g_head[45 * NPIX];

#define SWZ(o) ((uint32_t)(o) ^ ((((uint32_t)(o)) >> 3) & 0x70u))

__device__ __forceinline__ uint32_t smem_u32(const void* p) {
    uint32_t a;
    asm("{ .reg .u64 t; cvta.to.shared.u64 t, %1; cvt.u32.u64 %0, t; }"
        : "=r"(a) : "l"(p));
    return a;
}
__device__ __forceinline__ void cpa16(uint32_t dst, const void* src) {
    asm volatile("cp.async.cg.shared.global [%0], [%1], 16;"
                 :: "r"(dst), "l"(src) : "memory");
}
__device__ __forceinline__ void ldsm4(uint32_t* r, uint32_t addr) {
    asm volatile("ldmatrix.sync.aligned.m8n8.x4.shared.b16 {%0,%1,%2,%3}, [%4];"
                 : "=r"(r[0]), "=r"(r[1]), "=r"(r[2]), "=r"(r[3]) : "r"(addr));
}
__device__ __forceinline__ void ldsm2(uint32_t* r, uint32_t addr) {
    asm volatile("ldmatrix.sync.aligned.m8n8.x2.shared.b16 {%0,%1}, [%2];"
                 : "=r"(r[0]), "=r"(r[1]) : "r"(addr));
}
__device__ __forceinline__ void mma16816(float* d, const uint32_t* a, const uint32_t* b) {
    asm volatile(
        "mma.sync.aligned.m16n8k16.row.col.f32.f16.f16.f32 "
        "{%0,%1,%2,%3}, {%4,%5,%6,%7}, {%8,%9}, {%0,%1,%2,%3};"
        : "+f"(d[0]), "+f"(d[1]), "+f"(d[2]), "+f"(d[3])
        : "r"(a[0]), "r"(a[1]), "r"(a[2]), "r"(a[3]), "r"(b[0]), "r"(b[1]));
}
__device__ __forceinline__ void split_store(float v, __half* hi, __half* lo, size_t off) {
    __half h = __float2half_rn(v);
    hi[off] = h;
    lo[off] = __float2half_rn(v - __half2float(h));
}

// ----------------------- weight transform: u = G g G^T ---------------------
__global__ __launch_bounds__(256) void wtrans_kernel(const float* __restrict__ W) {
    int t = blockIdx.x * blockDim.x + threadIdx.x;   // t = oc*2048 + ic
    if (t >= 2048 * 2048) return;
    const float* g = W + (size_t)t * 9;
    float g0 = g[0], g1 = g[1], g2 = g[2];
    float g3 = g[3], g4 = g[4], g5 = g[5];
    float g6 = g[6], g7 = g[7], g8 = g[8];
    // T = G g  (4x3): rows
    float T[4][3];
    T[0][0] = g0; T[0][1] = g1; T[0][2] = g2;
    T[1][0] = 0.5f * (g0 + g3 + g6); T[1][1] = 0.5f * (g1 + g4 + g7); T[1][2] = 0.5f * (g2 + g5 + g8);
    T[2][0] = 0.5f * (g0 - g3 + g6); T[2][1] = 0.5f * (g1 - g4 + g7); T[2][2] = 0.5f * (g2 - g5 + g8);
    T[3][0] = g6; T[3][1] = g7; T[3][2] = g8;
    // u = T G^T (4x4): columns
    #pragma unroll
    for (int i = 0; i < 4; i++) {
        float u0 = T[i][0];
        float u1 = 0.5f * (T[i][0] + T[i][1] + T[i][2]);
        float u2 = 0.5f * (T[i][0] - T[i][1] + T[i][2]);
        float u3 = T[i][2];
        split_store(u0, g_Uhi, g_Ulo, (size_t)(4 * i + 0) * USTRIDE + t);
        split_store(u1, g_Uhi, g_Ulo, (size_t)(4 * i + 1) * USTRIDE + t);
        split_store(u2, g_Uhi, g_Ulo, (size_t)(4 * i + 2) * USTRIDE + t);
        split_store(u3, g_Uhi, g_Ulo, (size_t)(4 * i + 3) * USTRIDE + t);
    }
}

// ----------------------- input transform: d = B^T x B ----------------------
__global__ __launch_bounds__(256) void xtrans_kernel(const float* __restrict__ X) {
    int t = blockIdx.x * blockDim.x + threadIdx.x;   // t = tile*2048 + ic
    if (t >= NTP * 2048) return;
    int tile = t >> 11;
    int ic = t & 2047;
    if (tile >= NTIL) {
        #pragma unroll
        for (int p = 0; p < 16; p++) {
            g_Vhi[(size_t)p * VSTRIDE + t] = __float2half_rn(0.f);
            g_Vlo[(size_t)p * VSTRIDE + t] = __float2half_rn(0.f);
        }
        return;
    }
    int ti = tile / NT14, tj = tile - ti * NT14;
    const float* xp = X + (size_t)ic * NPIX;
    float x[4][4];
    #pragma unroll
    for (int r = 0; r < 4; r++) {
        int yy = 2 * ti - 1 + r;
        #pragma unroll
        for (int cq = 0; cq < 4; cq++) {
            int xx = 2 * tj - 1 + cq;
            x[r][cq] = ((unsigned)yy < 28u && (unsigned)xx < 28u)
                       ? __ldg(&xp[yy * 28 + xx]) : 0.f;
        }
    }
    // T = B^T x: rows
    float T[4][4];
    #pragma unroll
    for (int j = 0; j < 4; j++) {
        T[0][j] = x[0][j] - x[2][j];
        T[1][j] = x[1][j] + x[2][j];
        T[2][j] = x[2][j] - x[1][j];
        T[3][j] = x[1][j] - x[3][j];
    }
    // d = T B: columns
    #pragma unroll
    for (int i = 0; i < 4; i++) {
        float d0 = T[i][0] - T[i][2];
        float d1 = T[i][1] + T[i][2];
        float d2 = T[i][2] - T[i][1];
        float d3 = T[i][1] - T[i][3];
        split_store(d0, g_Vhi, g_Vlo, (size_t)(4 * i + 0) * VSTRIDE + t);
        split_store(d1, g_Vhi, g_Vlo, (size_t)(4 * i + 1) * VSTRIDE + t);
        split_store(d2, g_Vhi, g_Vlo, (size_t)(4 * i + 2) * VSTRIDE + t);
        split_store(d3, g_Vhi, g_Vlo, (size_t)(4 * i + 3) * VSTRIDE + t);
    }
}

// --------------------- Winograd GEMM: m[p] = U[p] @ V[p]^T -----------------
__global__ __launch_bounds__(256, 1) void wino_mma_kernel() {
    extern __shared__ char smraw[];
    uintptr_t basep = ((uintptr_t)smraw + 1023) & ~(uintptr_t)1023;
    const uint32_t smb = smem_u32((void*)basep);

    const int tid  = threadIdx.x;
    const int wid  = tid >> 5;
    const int lane = tid & 31;
    const int wm   = (wid & 3) * 32;
    const int wn   = (wid >> 2) * 56;
    const int n0   = blockIdx.x * TN;
    const int m0   = blockIdx.y * TM;
    const int pos  = blockIdx.z;

    const __half* Ahi = g_Uhi + (size_t)pos * USTRIDE;
    const __half* Alo = g_Ulo + (size_t)pos * USTRIDE;
    const __half* Bhi = g_Vhi + (size_t)pos * VSTRIDE;
    const __half* Blo = g_Vlo + (size_t)pos * VSTRIDE;

    uint32_t aoff[2], boff[7];
    {
        int arow = wm + (lane & 15);
        int acol = (lane >> 4) * 16;
        #pragma unroll
        for (int mt = 0; mt < 2; mt++)
            aoff[mt] = SWZ((arow + mt * 16) * 128 + acol);
        int bi = lane & 15;
        int brow = wn + (bi & 7);
        int bcol = ((bi >> 3) & 1) * 16;
        #pragma unroll
        for (int nt = 0; nt < 7; nt++)
            boff[nt] = SWZ((brow + nt * 8) * 128 + bcol);
    }

    float acc[2][7][4];
    #pragma unroll
    for (int mt = 0; mt < 2; mt++)
        #pragma unroll
        for (int nt = 0; nt < 7; nt++)
            #pragma unroll
            for (int i = 0; i < 4; i++) acc[mt][nt][i] = 0.f;

    auto load_stage = [&](int it) {
        const int stg = it % NSTG;
        const uint32_t sb = smb + stg * STG_SZ;
        const int kc = it * KC;
        #pragma unroll
        for (int q = tid; q < 1024; q += 256) {           // A: 128 rows x 8
            int r = q >> 3, c = q & 7;
            uint32_t so = SWZ(r * 128 + c * 16);
            size_t go = (size_t)(m0 + r) * KDIM + kc + c * 8;
            cpa16(sb + OFF_AH + so, Ahi + go);
            cpa16(sb + OFF_AL + so, Alo + go);
        }
        #pragma unroll
        for (int q = tid; q < 896; q += 256) {            // B: 112 rows x 8
            int r = q >> 3, c = q & 7;
            uint32_t so = SWZ(r * 128 + c * 16);
            size_t go = (size_t)(n0 + r) * KDIM + kc + c * 8;
            cpa16(sb + OFF_BH + so, Bhi + go);
            cpa16(sb + OFF_BL + so, Blo + go);
        }
    };

    load_stage(0);
    asm volatile("cp.async.commit_group;" ::: "memory");
    load_stage(1);
    asm volatile("cp.async.commit_group;" ::: "memory");

    for (int c = 0; c < NCH; ++c) {
        asm volatile("cp.async.wait_group 1;" ::: "memory");
        __syncthreads();

        if (c + 2 < NCH) load_stage(c + 2);
        asm volatile("cp.async.commit_group;" ::: "memory");

        const uint32_t sb = smb + (c % NSTG) * STG_SZ;
        #pragma unroll
        for (int kk = 0; kk < 4; kk++) {
            const uint32_t kd = kk * 32;
            uint32_t ah[2][4], al[2][4], bh[7][2], bl[7][2];
            #pragma unroll
            for (int mt = 0; mt < 2; mt++) {
                ldsm4(ah[mt], sb + OFF_AH + (aoff[mt] ^ kd));
                ldsm4(al[mt], sb + OFF_AL + (aoff[mt] ^ kd));
            }
            #pragma unroll
            for (int nt = 0; nt < 7; nt++) {
                ldsm2(bh[nt], sb + OFF_BH + (boff[nt] ^ kd));
                ldsm2(bl[nt], sb + OFF_BL + (boff[nt] ^ kd));
            }
            #pragma unroll
            for (int mt = 0; mt < 2; mt++)
                #pragma unroll
                for (int nt = 0; nt < 7; nt++) {
                    mma16816(acc[mt][nt], ah[mt], bh[nt]);
                    mma16816(acc[mt][nt], ah[mt], bl[nt]);
                    mma16816(acc[mt][nt], al[mt], bh[nt]);
                }
        }
    }

    // epilogue: raw m values -> g_m[pos][oc][tile]
    const int l4 = lane >> 2;
    const int l2 = (lane & 3) * 2;
    float* mdst = g_m + (size_t)pos * MSTRIDE;
    #pragma unroll
    for (int mt = 0; mt < 2; mt++) {
        int ocA = m0 + wm + mt * 16 + l4;
        int ocB = ocA + 8;
        #pragma unroll
        for (int nt = 0; nt < 7; nt++) {
            int col = n0 + wn + nt * 8 + l2;
            float2 vA, vB;
            vA.x = acc[mt][nt][0]; vA.y = acc[mt][nt][1];
            vB.x = acc[mt][nt][2]; vB.y = acc[mt][nt][3];
            *(float2*)(mdst + (size_t)ocA * NTP + col) = vA;
            *(float2*)(mdst + (size_t)ocB * NTP + col) = vB;
        }
    }
}

// ------------------- inverse transform: y = A^T m A + bias, relu -----------
__global__ __launch_bounds__(256) void itrans_kernel(const float* __restrict__ CB) {
    int t = blockIdx.x * blockDim.x + threadIdx.x;   // t = oc*196 + tile
    if (t >= 2048 * NTIL) return;
    int oc = t / NTIL;
    int tile = t - oc * NTIL;
    int ti = tile / NT14, tj = tile - ti * NT14;

    float m[16];
    #pragma unroll
    for (int p = 0; p < 16; p++)
        m[p] = g_m[(size_t)p * MSTRIDE + (size_t)oc * NTP + tile];

    float T0[4], T1[4];
    #pragma unroll
    for (int j = 0; j < 4; j++) {
        T0[j] = m[j] + m[4 + j] + m[8 + j];
        T1[j] = m[4 + j] - m[8 + j] - m[12 + j];
    }
    float y00 = T0[0] + T0[1] + T0[2];
    float y01 = T0[1] - T0[2] - T0[3];
    float y10 = T1[0] + T1[1] + T1[2];
    float y11 = T1[1] - T1[2] - T1[3];

    float bias = __ldg(&CB[oc]);
    float* hp = g_h + (size_t)oc * NPIX;
    int oy = 2 * ti, ox = 2 * tj;
    hp[oy * 28 + ox]           = fmaxf(y00 + bias, 0.f);
    hp[oy * 28 + ox + 1]       = fmaxf(y01 + bias, 0.f);
    hp[(oy + 1) * 28 + ox]     = fmaxf(y10 + bias, 0.f);
    hp[(oy + 1) * 28 + ox + 1] = fmaxf(y11 + bias, 0.f);
}

// --------------------- transpose g_h[ch][pix] -> g_ht[pix][ch] -------------
__global__ void transpose_kernel() {
    __shared__ float ts[32][33];
    int cb = blockIdx.x * 32;        // channel base
    int pb = blockIdx.y * 32;        // pixel base
    int tx = threadIdx.x, ty = threadIdx.y;
    #pragma unroll
    for (int j = 0; j < 4; j++) {
        int ch = cb + ty + j * 8;
        int p = pb + tx;
        if (p < NPIX) ts[ty + j * 8][tx] = g_h[(size_t)ch * NPIX + p];
    }
    __syncthreads();
    #pragma unroll
    for (int j = 0; j < 4; j++) {
        int p = pb + ty + j * 8;
        int ch = cb + tx;
        if (p < NPIX) g_ht[(size_t)p * 2048 + ch] = ts[tx][ty + j * 8];
    }
}

// ------------------------------- heads -------------------------------------
// 98 blocks x 8 warps; warp per pixel; coalesced via g_ht.
__global__ __launch_bounds__(256) void heads_kernel(
    const float* __restrict__ reg_w, const float* __restrict__ reg_b,
    const float* __restrict__ cls_w, const float* __restrict__ cls_b)
{
    const int lane = threadIdx.x & 31;
    const int warp = threadIdx.x >> 5;
    const int p = blockIdx.x * 8 + warp;

    float4 hv[16];
    #pragma unroll
    for (int j = 0; j < 16; j++)
        hv[j] = __ldg((const float4*)(g_ht + (size_t)p * 2048 + lane * 4 + 128 * j));

    #pragma unroll 1
    for (int o = 0; o < 45; o++) {
        const float* w = (o < 36) ? (reg_w + o * 2048) : (cls_w + (o - 36) * 2048);
        float s = 0.f;
        #pragma unroll
        for (int j = 0; j < 16; j++) {
            float4 wq = __ldg((const float4*)(w + lane * 4 + 128 * j));
            s += hv[j].x * wq.x + hv[j].y * wq.y + hv[j].z * wq.z + hv[j].w * wq.w;
        }
        #pragma unroll
        for (int off = 16; off > 0; off >>= 1) s += __shfl_xor_sync(0xffffffffu, s, off);
        if (lane == 0) {
            float b = (o < 36) ? __ldg(&reg_b[o]) : __ldg(&cls_b[o - 36]);
            g_head[o * NPIX + p] = 1.f / (1.f + expf(-(s + b)));
        }
    }
}

// ------------------------- scan + gather (fused) ---------------------------
__device__ __forceinline__ bool anchor_valid(int j) {
    int a = j % 9, p = j / 9;
    int y = p / 28, x = p % 28;
    double scale = (a / 3 == 0) ? 64.0 : (a / 3 == 1) ? 128.0 : 256.0;
    double ratio = (a % 3 == 0) ? 0.5 : (a % 3 == 1) ? 1.0 : 2.0;
    double hh = scale / sqrt(ratio) / 448.0;
    double ww = scale * sqrt(ratio) / 448.0;
    double cy = ((double)y + 0.5) / 28.0;
    double cx = ((double)x + 0.5) / 28.0;
    double y1 = cy - hh / 2.0, x1 = cx - ww / 2.0;
    double y2 = cy + hh / 2.0, x2 = cx + ww / 2.0;
    return (y1 > 0.0) && (x1 > 0.0) && (y2 < 28.0) && (x2 < 28.0);
}

__global__ void scan_gather_kernel(float* __restrict__ out) {
    __shared__ int s[1024];
    const int tid = threadIdx.x;
    const int base = tid * 7;
    int f[7];
    int cnt = 0;
    #pragma unroll
    for (int i = 0; i < 7; i++) {
        int j = base + i;
        f[i] = (j < 7056 && anchor_valid(j)) ? 1 : 0;
        cnt += f[i];
    }
    s[tid] = cnt;
    __syncthreads();
    for (int off = 1; off < 1024; off <<= 1) {
        int v = s[tid];
        int add = (tid >= off) ? s[tid - off] : 0;
        __syncthreads();
        s[tid] = v + add;
        __syncthreads();
    }
    int pos = s[tid] - cnt;
    #pragma unroll
    for (int i = 0; i < 7; i++) {
        int j = base + i;
        if (j < 7056 && f[i]) {
            int a = j / NPIX, p = j % NPIX;
            float cls = g_head[(36 + a) * NPIX + p];
            float k = (cls > 0.9f) ? 1.f : 0.f;
            #pragma unroll
            for (int c = 0; c < 4; c++)
                out[pos * 4 + c] = g_head[(c * 9 + a) * NPIX + p] * k;
            pos++;
        }
    }
}

// ---------------------------------------------------------------------------
extern "C" void kernel_launch(void* const* d_in, const int* in_sizes, int n_in,
                              void* d_out, int out_size)
{
    const float* x      = (const float*)d_in[0];
    const float* conv_w = (const float*)d_in[1];
    const float* conv_b = (const float*)d_in[2];
    const float* reg_w  = (const float*)d_in[3];
    const float* reg_b  = (const float*)d_in[4];
    const float* cls_w  = (const float*)d_in[5];
    const float* cls_b  = (const float*)d_in[6];
    float* out = (float*)d_out;

    cudaFuncSetAttribute(wino_mma_kernel,
                         cudaFuncAttributeMaxDynamicSharedMemorySize, CONV_SMEM);

    wtrans_kernel<<<(2048 * 2048 + 255) / 256, 256>>>(conv_w);
    xtrans_kernel<<<(NTP * 2048 + 255) / 256, 256>>>(x);
    wino_mma_kernel<<<dim3(2, 16, 16), 256, CONV_SMEM>>>();
    itrans_kernel<<<(2048 * NTIL + 255) / 256, 256>>>(conv_b);
    transpose_kernel<<<dim3(64, 25), dim3(32, 8)>>>();
    heads_kernel<<<98, 256>>>(reg_w, reg_b, cls_w, cls_b);
    scan_gather_kernel<<<1, 1024>>>(out);
}

// round 7
// speedup vs baseline: 5.5139x; 1.5025x over previous
#include <cuda_runtime.h>
#include <cuda_fp16.h>
#include <math.h>
#include <stdint.h>

// ---------------------------------------------------------------------------
// RPN round 7: Winograd F(2x2,3x3) + split-fp16 HMMA GEMMs.
//  - transforms vectorized (uint2 stores, 4 pairs/thread)
//  - GEMM split-K2 into two buffers (finer jobs, no wave tail), summed in itrans
// ---------------------------------------------------------------------------

#define NPIX  784
#define NT14  14
#define NTIL  196
#define NTP   224
#define KDIM  2048
#define KC    64
#define NCHH  16               // chunks per K-slice (K=1024)
#define TM    128
#define TN    112
#define NSTG  3
#define A_BYTES (TM * 128)
#define B_BYTES (TN * 128)
#define STG_SZ  (2 * A_BYTES + 2 * B_BYTES)
#define OFF_AH  0
#define OFF_AL  A_BYTES
#define OFF_BH  (2 * A_BYTES)
#define OFF_BL  (2 * A_BYTES + B_BYTES)
#define CONV_SMEM (NSTG * STG_SZ + 1024)

#define USTRIDE (2048 * 2048)
#define VSTRIDE (NTP * 2048)
#define MSTRIDE (2048 * NTP)

__device__ __half g_Uhi[16 * USTRIDE];
__device__ __half g_Ulo[16 * USTRIDE];
__device__ __half g_Vhi[16 * VSTRIDE];
__device__ __half g_Vlo[16 * VSTRIDE];
__device__ float  g_m[2][16 * MSTRIDE];     // split-K partials
__device__ float  g_h[2048 * NPIX];
__device__ float  g_ht[NPIX * 2048];
__device__ float  g_head[45 * NPIX];

#define SWZ(o) ((uint32_t)(o) ^ ((((uint32_t)(o)) >> 3) & 0x70u))

__device__ __forceinline__ uint32_t smem_u32(const void* p) {
    uint32_t a;
    asm("{ .reg .u64 t; cvta.to.shared.u64 t, %1; cvt.u32.u64 %0, t; }"
        : "=r"(a) : "l"(p));
    return a;
}
__device__ __forceinline__ void cpa16(uint32_t dst, const void* src) {
    asm volatile("cp.async.cg.shared.global [%0], [%1], 16;"
                 :: "r"(dst), "l"(src) : "memory");
}
__device__ __forceinline__ void ldsm4(uint32_t* r, uint32_t addr) {
    asm volatile("ldmatrix.sync.aligned.m8n8.x4.shared.b16 {%0,%1,%2,%3}, [%4];"
                 : "=r"(r[0]), "=r"(r[1]), "=r"(r[2]), "=r"(r[3]) : "r"(addr));
}
__device__ __forceinline__ void ldsm2(uint32_t* r, uint32_t addr) {
    asm volatile("ldmatrix.sync.aligned.m8n8.x2.shared.b16 {%0,%1}, [%2];"
                 : "=r"(r[0]), "=r"(r[1]) : "r"(addr));
}
__device__ __forceinline__ void mma16816(float* d, const uint32_t* a, const uint32_t* b) {
    asm volatile(
        "mma.sync.aligned.m16n8k16.row.col.f32.f16.f16.f32 "
        "{%0,%1,%2,%3}, {%4,%5,%6,%7}, {%8,%9}, {%0,%1,%2,%3};"
        : "+f"(d[0]), "+f"(d[1]), "+f"(d[2]), "+f"(d[3])
        : "r"(a[0]), "r"(a[1]), "r"(a[2]), "r"(a[3]), "r"(b[0]), "r"(b[1]));
}
__device__ __forceinline__ ushort hi_part(float v, float& rem) {
    __half h = __float2half_rn(v);
    rem = v - __half2float(h);
    return *(ushort*)&h;
}

// ----------------------- weight transform: u = G g G^T ---------------------
// Each thread: 4 consecutive (oc,ic) pairs; per position writes uint2 (4 halves).
__global__ __launch_bounds__(256) void wtrans_kernel(const float* __restrict__ W) {
    int q = blockIdx.x * blockDim.x + threadIdx.x;
    const int nq = (2048 * 2048) / 4;
    if (q >= nq) return;
    const int t0 = q * 4;

    ushort uhi[16][4], ulo[16][4];
    #pragma unroll
    for (int j = 0; j < 4; j++) {
        const float* g = W + (size_t)(t0 + j) * 9;
        float g0 = __ldg(g + 0), g1 = __ldg(g + 1), g2 = __ldg(g + 2);
        float g3 = __ldg(g + 3), g4 = __ldg(g + 4), g5 = __ldg(g + 5);
        float g6 = __ldg(g + 6), g7 = __ldg(g + 7), g8 = __ldg(g + 8);
        float T[4][3];
        T[0][0] = g0; T[0][1] = g1; T[0][2] = g2;
        T[1][0] = 0.5f * (g0 + g3 + g6); T[1][1] = 0.5f * (g1 + g4 + g7); T[1][2] = 0.5f * (g2 + g5 + g8);
        T[2][0] = 0.5f * (g0 - g3 + g6); T[2][1] = 0.5f * (g1 - g4 + g7); T[2][2] = 0.5f * (g2 - g5 + g8);
        T[3][0] = g6; T[3][1] = g7; T[3][2] = g8;
        #pragma unroll
        for (int i = 0; i < 4; i++) {
            float u[4];
            u[0] = T[i][0];
            u[1] = 0.5f * (T[i][0] + T[i][1] + T[i][2]);
            u[2] = 0.5f * (T[i][0] - T[i][1] + T[i][2]);
            u[3] = T[i][2];
            #pragma unroll
            for (int c = 0; c < 4; c++) {
                float rem;
                uhi[4 * i + c][j] = hi_part(u[c], rem);
                __half lo = __float2half_rn(rem);
                ulo[4 * i + c][j] = *(ushort*)&lo;
            }
        }
    }
    #pragma unroll
    for (int p = 0; p < 16; p++) {
        *(uint2*)(g_Uhi + (size_t)p * USTRIDE + t0) = *(uint2*)uhi[p];
        *(uint2*)(g_Ulo + (size_t)p * USTRIDE + t0) = *(uint2*)ulo[p];
    }
}

// ----------------------- input transform: d = B^T x B ----------------------
// Thread: 4 consecutive ic for one tile; vectorized uint2 stores.
__global__ __launch_bounds__(256) void xtrans_kernel(const float* __restrict__ X) {
    int q = blockIdx.x * blockDim.x + threadIdx.x;
    const int nq = (NTP * 2048) / 4;
    if (q >= nq) return;
    const int t0 = q * 4;
    const int tile = t0 >> 11;
    const int ic0 = t0 & 2047;

    ushort dhi[16][4], dlo[16][4];
    if (tile >= NTIL) {
        #pragma unroll
        for (int p = 0; p < 16; p++) {
            *(uint2*)(g_Vhi + (size_t)p * VSTRIDE + t0) = make_uint2(0u, 0u);
            *(uint2*)(g_Vlo + (size_t)p * VSTRIDE + t0) = make_uint2(0u, 0u);
        }
        return;
    }
    const int ti = tile / NT14, tj = tile - ti * NT14;
    #pragma unroll
    for (int j = 0; j < 4; j++) {
        const float* xp = X + (size_t)(ic0 + j) * NPIX;
        float x[4][4];
        #pragma unroll
        for (int r = 0; r < 4; r++) {
            int yy = 2 * ti - 1 + r;
            #pragma unroll
            for (int cq = 0; cq < 4; cq++) {
                int xx = 2 * tj - 1 + cq;
                x[r][cq] = ((unsigned)yy < 28u && (unsigned)xx < 28u)
                           ? __ldg(&xp[yy * 28 + xx]) : 0.f;
            }
        }
        float T[4][4];
        #pragma unroll
        for (int c = 0; c < 4; c++) {
            T[0][c] = x[0][c] - x[2][c];
            T[1][c] = x[1][c] + x[2][c];
            T[2][c] = x[2][c] - x[1][c];
            T[3][c] = x[1][c] - x[3][c];
        }
        #pragma unroll
        for (int i = 0; i < 4; i++) {
            float d[4];
            d[0] = T[i][0] - T[i][2];
            d[1] = T[i][1] + T[i][2];
            d[2] = T[i][2] - T[i][1];
            d[3] = T[i][1] - T[i][3];
            #pragma unroll
            for (int c = 0; c < 4; c++) {
                float rem;
                dhi[4 * i + c][j] = hi_part(d[c], rem);
                __half lo = __float2half_rn(rem);
                dlo[4 * i + c][j] = *(ushort*)&lo;
            }
        }
    }
    #pragma unroll
    for (int p = 0; p < 16; p++) {
        *(uint2*)(g_Vhi + (size_t)p * VSTRIDE + t0) = *(uint2*)dhi[p];
        *(uint2*)(g_Vlo + (size_t)p * VSTRIDE + t0) = *(uint2*)dlo[p];
    }
}

// --------------------- Winograd GEMM (split-K2) ----------------------------
// grid (2, 16, 32): x=N tile, y=M tile, z = pos*2 + kslice
__global__ __launch_bounds__(256, 1) void wino_mma_kernel() {
    extern __shared__ char smraw[];
    uintptr_t basep = ((uintptr_t)smraw + 1023) & ~(uintptr_t)1023;
    const uint32_t smb = smem_u32((void*)basep);

    const int tid  = threadIdx.x;
    const int wid  = tid >> 5;
    const int lane = tid & 31;
    const int wm   = (wid & 3) * 32;
    const int wn   = (wid >> 2) * 56;
    const int n0   = blockIdx.x * TN;
    const int m0   = blockIdx.y * TM;
    const int pos  = blockIdx.z >> 1;
    const int ksl  = blockIdx.z & 1;
    const int kbase = ksl * (NCHH * KC);

    const __half* Ahi = g_Uhi + (size_t)pos * USTRIDE;
    const __half* Alo = g_Ulo + (size_t)pos * USTRIDE;
    const __half* Bhi = g_Vhi + (size_t)pos * VSTRIDE;
    const __half* Blo = g_Vlo + (size_t)pos * VSTRIDE;

    uint32_t aoff[2], boff[7];
    {
        int arow = wm + (lane & 15);
        int acol = (lane >> 4) * 16;
        #pragma unroll
        for (int mt = 0; mt < 2; mt++)
            aoff[mt] = SWZ((arow + mt * 16) * 128 + acol);
        int bi = lane & 15;
        int brow = wn + (bi & 7);
        int bcol = ((bi >> 3) & 1) * 16;
        #pragma unroll
        for (int nt = 0; nt < 7; nt++)
            boff[nt] = SWZ((brow + nt * 8) * 128 + bcol);
    }

    float acc[2][7][4];
    #pragma unroll
    for (int mt = 0; mt < 2; mt++)
        #pragma unroll
        for (int nt = 0; nt < 7; nt++)
            #pragma unroll
            for (int i = 0; i < 4; i++) acc[mt][nt][i] = 0.f;

    auto load_stage = [&](int it) {
        const int stg = it % NSTG;
        const uint32_t sb = smb + stg * STG_SZ;
        const int kc = kbase + it * KC;
        #pragma unroll
        for (int q = tid; q < 1024; q += 256) {
            int r = q >> 3, c = q & 7;
            uint32_t so = SWZ(r * 128 + c * 16);
            size_t go = (size_t)(m0 + r) * KDIM + kc + c * 8;
            cpa16(sb + OFF_AH + so, Ahi + go);
            cpa16(sb + OFF_AL + so, Alo + go);
        }
        #pragma unroll
        for (int q = tid; q < 896; q += 256) {
            int r = q >> 3, c = q & 7;
            uint32_t so = SWZ(r * 128 + c * 16);
            size_t go = (size_t)(n0 + r) * KDIM + kc + c * 8;
            cpa16(sb + OFF_BH + so, Bhi + go);
            cpa16(sb + OFF_BL + so, Blo + go);
        }
    };

    load_stage(0);
    asm volatile("cp.async.commit_group;" ::: "memory");
    load_stage(1);
    asm volatile("cp.async.commit_group;" ::: "memory");

    for (int c = 0; c < NCHH; ++c) {
        asm volatile("cp.async.wait_group 1;" ::: "memory");
        __syncthreads();

        if (c + 2 < NCHH) load_stage(c + 2);
        asm volatile("cp.async.commit_group;" ::: "memory");

        const uint32_t sb = smb + (c % NSTG) * STG_SZ;
        #pragma unroll
        for (int kk = 0; kk < 4; kk++) {
            const uint32_t kd = kk * 32;
            uint32_t ah[2][4], al[2][4], bh[7][2], bl[7][2];
            #pragma unroll
            for (int mt = 0; mt < 2; mt++) {
                ldsm4(ah[mt], sb + OFF_AH + (aoff[mt] ^ kd));
                ldsm4(al[mt], sb + OFF_AL + (aoff[mt] ^ kd));
            }
            #pragma unroll
            for (int nt = 0; nt < 7; nt++) {
                ldsm2(bh[nt], sb + OFF_BH + (boff[nt] ^ kd));
                ldsm2(bl[nt], sb + OFF_BL + (boff[nt] ^ kd));
            }
            #pragma unroll
            for (int mt = 0; mt < 2; mt++)
                #pragma unroll
                for (int nt = 0; nt < 7; nt++) {
                    mma16816(acc[mt][nt], ah[mt], bh[nt]);
                    mma16816(acc[mt][nt], ah[mt], bl[nt]);
                    mma16816(acc[mt][nt], al[mt], bh[nt]);
                }
        }
    }

    const int l4 = lane >> 2;
    const int l2 = (lane & 3) * 2;
    float* mdst = g_m[ksl] + (size_t)pos * MSTRIDE;
    #pragma unroll
    for (int mt = 0; mt < 2; mt++) {
        int ocA = m0 + wm + mt * 16 + l4;
        int ocB = ocA + 8;
        #pragma unroll
        for (int nt = 0; nt < 7; nt++) {
            int col = n0 + wn + nt * 8 + l2;
            float2 vA, vB;
            vA.x = acc[mt][nt][0]; vA.y = acc[mt][nt][1];
            vB.x = acc[mt][nt][2]; vB.y = acc[mt][nt][3];
            *(float2*)(mdst + (size_t)ocA * NTP + col) = vA;
            *(float2*)(mdst + (size_t)ocB * NTP + col) = vB;
        }
    }
}

// ------------------- inverse transform: y = A^T m A + bias, relu -----------
__global__ __launch_bounds__(256) void itrans_kernel(const float* __restrict__ CB) {
    int t = blockIdx.x * blockDim.x + threadIdx.x;
    if (t >= 2048 * NTIL) return;
    int oc = t / NTIL;
    int tile = t - oc * NTIL;
    int ti = tile / NT14, tj = tile - ti * NT14;

    float m[16];
    #pragma unroll
    for (int p = 0; p < 16; p++) {
        size_t off = (size_t)p * MSTRIDE + (size_t)oc * NTP + tile;
        m[p] = g_m[0][off] + g_m[1][off];
    }

    float T0[4], T1[4];
    #pragma unroll
    for (int j = 0; j < 4; j++) {
        T0[j] = m[j] + m[4 + j] + m[8 + j];
        T1[j] = m[4 + j] - m[8 + j] - m[12 + j];
    }
    float y00 = T0[0] + T0[1] + T0[2];
    float y01 = T0[1] - T0[2] - T0[3];
    float y10 = T1[0] + T1[1] + T1[2];
    float y11 = T1[1] - T1[2] - T1[3];

    float bias = __ldg(&CB[oc]);
    float* hp = g_h + (size_t)oc * NPIX;
    int oy = 2 * ti, ox = 2 * tj;
    hp[oy * 28 + ox]           = fmaxf(y00 + bias, 0.f);
    hp[oy * 28 + ox + 1]       = fmaxf(y01 + bias, 0.f);
    hp[(oy + 1) * 28 + ox]     = fmaxf(y10 + bias, 0.f);
    hp[(oy + 1) * 28 + ox + 1] = fmaxf(y11 + bias, 0.f);
}

// --------------------- transpose g_h[ch][pix] -> g_ht[pix][ch] -------------
__global__ void transpose_kernel() {
    __shared__ float ts[32][33];
    int cb = blockIdx.x * 32;
    int pb = blockIdx.y * 32;
    int tx = threadIdx.x, ty = threadIdx.y;
    #pragma unroll
    for (int j = 0; j < 4; j++) {
        int ch = cb + ty + j * 8;
        int p = pb + tx;
        if (p < NPIX) ts[ty + j * 8][tx] = g_h[(size_t)ch * NPIX + p];
    }
    __syncthreads();
    #pragma unroll
    for (int j = 0; j < 4; j++) {
        int p = pb + ty + j * 8;
        int ch = cb + tx;
        if (p < NPIX) g_ht[(size_t)p * 2048 + ch] = ts[tx][ty + j * 8];
    }
}

// ------------------------------- heads -------------------------------------
__global__ __launch_bounds__(256) void heads_kernel(
    const float* __restrict__ reg_w, const float* __restrict__ reg_b,
    const float* __restrict__ cls_w, const float* __restrict__ cls_b)
{
    const int lane = threadIdx.x & 31;
    const int warp = threadIdx.x >> 5;
    const int p = blockIdx.x * 8 + warp;

    float4 hv[16];
    #pragma unroll
    for (int j = 0; j < 16; j++)
        hv[j] = __ldg((const float4*)(g_ht + (size_t)p * 2048 + lane * 4 + 128 * j));

    #pragma unroll 1
    for (int o = 0; o < 45; o++) {
        const float* w = (o < 36) ? (reg_w + o * 2048) : (cls_w + (o - 36) * 2048);
        float s = 0.f;
        #pragma unroll
        for (int j = 0; j < 16; j++) {
            float4 wq = __ldg((const float4*)(w + lane * 4 + 128 * j));
            s += hv[j].x * wq.x + hv[j].y * wq.y + hv[j].z * wq.z + hv[j].w * wq.w;
        }
        #pragma unroll
        for (int off = 16; off > 0; off >>= 1) s += __shfl_xor_sync(0xffffffffu, s, off);
        if (lane == 0) {
            float b = (o < 36) ? __ldg(&reg_b[o]) : __ldg(&cls_b[o - 36]);
            g_head[o * NPIX + p] = 1.f / (1.f + expf(-(s + b)));
        }
    }
}

// ------------------------- scan + gather (fused) ---------------------------
__device__ __forceinline__ bool anchor_valid(int j) {
    int a = j % 9, p = j / 9;
    int y = p / 28, x = p % 28;
    double scale = (a / 3 == 0) ? 64.0 : (a / 3 == 1) ? 128.0 : 256.0;
    double ratio = (a % 3 == 0) ? 0.5 : (a % 3 == 1) ? 1.0 : 2.0;
    double hh = scale / sqrt(ratio) / 448.0;
    double ww = scale * sqrt(ratio) / 448.0;
    double cy = ((double)y + 0.5) / 28.0;
    double cx = ((double)x + 0.5) / 28.0;
    double y1 = cy - hh / 2.0, x1 = cx - ww / 2.0;
    double y2 = cy + hh / 2.0, x2 = cx + ww / 2.0;
    return (y1 > 0.0) && (x1 > 0.0) && (y2 < 28.0) && (x2 < 28.0);
}

__global__ void scan_gather_kernel(float* __restrict__ out) {
    __shared__ int s[1024];
    const int tid = threadIdx.x;
    const int base = tid * 7;
    int f[7];
    int cnt = 0;
    #pragma unroll
    for (int i = 0; i < 7; i++) {
        int j = base + i;
        f[i] = (j < 7056 && anchor_valid(j)) ? 1 : 0;
        cnt += f[i];
    }
    s[tid] = cnt;
    __syncthreads();
    for (int off = 1; off < 1024; off <<= 1) {
        int v = s[tid];
        int add = (tid >= off) ? s[tid - off] : 0;
        __syncthreads();
        s[tid] = v + add;
        __syncthreads();
    }
    int pos = s[tid] - cnt;
    #pragma unroll
    for (int i = 0; i < 7; i++) {
        int j = base + i;
        if (j < 7056 && f[i]) {
            int a = j / NPIX, p = j % NPIX;
            float cls = g_head[(36 + a) * NPIX + p];
            float k = (cls > 0.9f) ? 1.f : 0.f;
            #pragma unroll
            for (int c = 0; c < 4; c++)
                out[pos * 4 + c] = g_head[(c * 9 + a) * NPIX + p] * k;
            pos++;
        }
    }
}

// ---------------------------------------------------------------------------
extern "C" void kernel_launch(void* const* d_in, const int* in_sizes, int n_in,
                              void* d_out, int out_size)
{
    const float* x      = (const float*)d_in[0];
    const float* conv_w = (const float*)d_in[1];
    const float* conv_b = (const float*)d_in[2];
    const float* reg_w  = (const float*)d_in[3];
    const float* reg_b  = (const float*)d_in[4];
    const float* cls_w  = (const float*)d_in[5];
    const float* cls_b  = (const float*)d_in[6];
    float* out = (float*)d_out;

    cudaFuncSetAttribute(wino_mma_kernel,
                         cudaFuncAttributeMaxDynamicSharedMemorySize, CONV_SMEM);

    wtrans_kernel<<<(2048 * 2048 / 4 + 255) / 256, 256>>>(conv_w);
    xtrans_kernel<<<(NTP * 2048 / 4 + 255) / 256, 256>>>(x);
    wino_mma_kernel<<<dim3(2, 16, 32), 256, CONV_SMEM>>>();
    itrans_kernel<<<(2048 * NTIL + 255) / 256, 256>>>(conv_b);
    transpose_kernel<<<dim3(64, 25), dim3(32, 8)>>>();
    heads_kernel<<<98, 256>>>(reg_w, reg_b, cls_w, cls_b);
    scan_gather_kernel<<<1, 1024>>>(out);
}

// round 8
// speedup vs baseline: 5.6047x; 1.0165x over previous
#include <cuda_runtime.h>
#include <cuda_fp16.h>
#include <math.h>
#include <stdint.h>

// ---------------------------------------------------------------------------
// RPN round 8: Winograd F(2x2,3x3) + split-fp16 HMMA GEMMs (split-K2).
//  R8 change: wtrans loads W via 9 aligned float4 per thread (was 36 scalar).
// ---------------------------------------------------------------------------

#define NPIX  784
#define NT14  14
#define NTIL  196
#define NTP   224
#define KDIM  2048
#define KC    64
#define NCHH  16               // chunks per K-slice (K=1024)
#define TM    128
#define TN    112
#define NSTG  3
#define A_BYTES (TM * 128)
#define B_BYTES (TN * 128)
#define STG_SZ  (2 * A_BYTES + 2 * B_BYTES)
#define OFF_AH  0
#define OFF_AL  A_BYTES
#define OFF_BH  (2 * A_BYTES)
#define OFF_BL  (2 * A_BYTES + B_BYTES)
#define CONV_SMEM (NSTG * STG_SZ + 1024)

#define USTRIDE (2048 * 2048)
#define VSTRIDE (NTP * 2048)
#define MSTRIDE (2048 * NTP)

__device__ __half g_Uhi[16 * USTRIDE];
__device__ __half g_Ulo[16 * USTRIDE];
__device__ __half g_Vhi[16 * VSTRIDE];
__device__ __half g_Vlo[16 * VSTRIDE];
__device__ float  g_m[2][16 * MSTRIDE];
__device__ float  g_h[2048 * NPIX];
__device__ float  g_ht[NPIX * 2048];
__device__ float  g_head[45 * NPIX];

#define SWZ(o) ((uint32_t)(o) ^ ((((uint32_t)(o)) >> 3) & 0x70u))

__device__ __forceinline__ uint32_t smem_u32(const void* p) {
    uint32_t a;
    asm("{ .reg .u64 t; cvta.to.shared.u64 t, %1; cvt.u32.u64 %0, t; }"
        : "=r"(a) : "l"(p));
    return a;
}
__device__ __forceinline__ void cpa16(uint32_t dst, const void* src) {
    asm volatile("cp.async.cg.shared.global [%0], [%1], 16;"
                 :: "r"(dst), "l"(src) : "memory");
}
__device__ __forceinline__ void ldsm4(uint32_t* r, uint32_t addr) {
    asm volatile("ldmatrix.sync.aligned.m8n8.x4.shared.b16 {%0,%1,%2,%3}, [%4];"
                 : "=r"(r[0]), "=r"(r[1]), "=r"(r[2]), "=r"(r[3]) : "r"(addr));
}
__device__ __forceinline__ void ldsm2(uint32_t* r, uint32_t addr) {
    asm volatile("ldmatrix.sync.aligned.m8n8.x2.shared.b16 {%0,%1}, [%2];"
                 : "=r"(r[0]), "=r"(r[1]) : "r"(addr));
}
__device__ __forceinline__ void mma16816(float* d, const uint32_t* a, const uint32_t* b) {
    asm volatile(
        "mma.sync.aligned.m16n8k16.row.col.f32.f16.f16.f32 "
        "{%0,%1,%2,%3}, {%4,%5,%6,%7}, {%8,%9}, {%0,%1,%2,%3};"
        : "+f"(d[0]), "+f"(d[1]), "+f"(d[2]), "+f"(d[3])
        : "r"(a[0]), "r"(a[1]), "r"(a[2]), "r"(a[3]), "r"(b[0]), "r"(b[1]));
}
__device__ __forceinline__ ushort hi_part(float v, float& rem) {
    __half h = __float2half_rn(v);
    rem = v - __half2float(h);
    return *(ushort*)&h;
}

// ----------------------- weight transform: u = G g G^T ---------------------
// Thread: 4 consecutive (oc,ic) pairs = 36 consecutive floats = 9 float4 loads.
__global__ __launch_bounds__(256) void wtrans_kernel(const float* __restrict__ W) {
    int q = blockIdx.x * blockDim.x + threadIdx.x;
    const int nq = (2048 * 2048) / 4;
    if (q >= nq) return;
    const int t0 = q * 4;

    float f[36];
    {
        const float4* w4 = (const float4*)(W + (size_t)t0 * 9);
        #pragma unroll
        for (int k = 0; k < 9; k++) {
            float4 v = __ldg(&w4[k]);
            f[4 * k + 0] = v.x; f[4 * k + 1] = v.y;
            f[4 * k + 2] = v.z; f[4 * k + 3] = v.w;
        }
    }

    ushort uhi[16][4], ulo[16][4];
    #pragma unroll
    for (int j = 0; j < 4; j++) {
        const float* g = f + j * 9;
        float g0 = g[0], g1 = g[1], g2 = g[2];
        float g3 = g[3], g4 = g[4], g5 = g[5];
        float g6 = g[6], g7 = g[7], g8 = g[8];
        float T[4][3];
        T[0][0] = g0; T[0][1] = g1; T[0][2] = g2;
        T[1][0] = 0.5f * (g0 + g3 + g6); T[1][1] = 0.5f * (g1 + g4 + g7); T[1][2] = 0.5f * (g2 + g5 + g8);
        T[2][0] = 0.5f * (g0 - g3 + g6); T[2][1] = 0.5f * (g1 - g4 + g7); T[2][2] = 0.5f * (g2 - g5 + g8);
        T[3][0] = g6; T[3][1] = g7; T[3][2] = g8;
        #pragma unroll
        for (int i = 0; i < 4; i++) {
            float u[4];
            u[0] = T[i][0];
            u[1] = 0.5f * (T[i][0] + T[i][1] + T[i][2]);
            u[2] = 0.5f * (T[i][0] - T[i][1] + T[i][2]);
            u[3] = T[i][2];
            #pragma unroll
            for (int c = 0; c < 4; c++) {
                float rem;
                uhi[4 * i + c][j] = hi_part(u[c], rem);
                __half lo = __float2half_rn(rem);
                ulo[4 * i + c][j] = *(ushort*)&lo;
            }
        }
    }
    #pragma unroll
    for (int p = 0; p < 16; p++) {
        *(uint2*)(g_Uhi + (size_t)p * USTRIDE + t0) = *(uint2*)uhi[p];
        *(uint2*)(g_Ulo + (size_t)p * USTRIDE + t0) = *(uint2*)ulo[p];
    }
}

// ----------------------- input transform: d = B^T x B ----------------------
__global__ __launch_bounds__(256) void xtrans_kernel(const float* __restrict__ X) {
    int q = blockIdx.x * blockDim.x + threadIdx.x;
    const int nq = (NTP * 2048) / 4;
    if (q >= nq) return;
    const int t0 = q * 4;
    const int tile = t0 >> 11;
    const int ic0 = t0 & 2047;

    ushort dhi[16][4], dlo[16][4];
    if (tile >= NTIL) {
        #pragma unroll
        for (int p = 0; p < 16; p++) {
            *(uint2*)(g_Vhi + (size_t)p * VSTRIDE + t0) = make_uint2(0u, 0u);
            *(uint2*)(g_Vlo + (size_t)p * VSTRIDE + t0) = make_uint2(0u, 0u);
        }
        return;
    }
    const int ti = tile / NT14, tj = tile - ti * NT14;
    #pragma unroll
    for (int j = 0; j < 4; j++) {
        const float* xp = X + (size_t)(ic0 + j) * NPIX;
        float x[4][4];
        #pragma unroll
        for (int r = 0; r < 4; r++) {
            int yy = 2 * ti - 1 + r;
            #pragma unroll
            for (int cq = 0; cq < 4; cq++) {
                int xx = 2 * tj - 1 + cq;
                x[r][cq] = ((unsigned)yy < 28u && (unsigned)xx < 28u)
                           ? __ldg(&xp[yy * 28 + xx]) : 0.f;
            }
        }
        float T[4][4];
        #pragma unroll
        for (int c = 0; c < 4; c++) {
            T[0][c] = x[0][c] - x[2][c];
            T[1][c] = x[1][c] + x[2][c];
            T[2][c] = x[2][c] - x[1][c];
            T[3][c] = x[1][c] - x[3][c];
        }
        #pragma unroll
        for (int i = 0; i < 4; i++) {
            float d[4];
            d[0] = T[i][0] - T[i][2];
            d[1] = T[i][1] + T[i][2];
            d[2] = T[i][2] - T[i][1];
            d[3] = T[i][1] - T[i][3];
            #pragma unroll
            for (int c = 0; c < 4; c++) {
                float rem;
                dhi[4 * i + c][j] = hi_part(d[c], rem);
                __half lo = __float2half_rn(rem);
                dlo[4 * i + c][j] = *(ushort*)&lo;
            }
        }
    }
    #pragma unroll
    for (int p = 0; p < 16; p++) {
        *(uint2*)(g_Vhi + (size_t)p * VSTRIDE + t0) = *(uint2*)dhi[p];
        *(uint2*)(g_Vlo + (size_t)p * VSTRIDE + t0) = *(uint2*)dlo[p];
    }
}

// --------------------- Winograd GEMM (split-K2) ----------------------------
__global__ __launch_bounds__(256, 1) void wino_mma_kernel() {
    extern __shared__ char smraw[];
    uintptr_t basep = ((uintptr_t)smraw + 1023) & ~(uintptr_t)1023;
    const uint32_t smb = smem_u32((void*)basep);

    const int tid  = threadIdx.x;
    const int wid  = tid >> 5;
    const int lane = tid & 31;
    const int wm   = (wid & 3) * 32;
    const int wn   = (wid >> 2) * 56;
    const int n0   = blockIdx.x * TN;
    const int m0   = blockIdx.y * TM;
    const int pos  = blockIdx.z >> 1;
    const int ksl  = blockIdx.z & 1;
    const int kbase = ksl * (NCHH * KC);

    const __half* Ahi = g_Uhi + (size_t)pos * USTRIDE;
    const __half* Alo = g_Ulo + (size_t)pos * USTRIDE;
    const __half* Bhi = g_Vhi + (size_t)pos * VSTRIDE;
    const __half* Blo = g_Vlo + (size_t)pos * VSTRIDE;

    uint32_t aoff[2], boff[7];
    {
        int arow = wm + (lane & 15);
        int acol = (lane >> 4) * 16;
        #pragma unroll
        for (int mt = 0; mt < 2; mt++)
            aoff[mt] = SWZ((arow + mt * 16) * 128 + acol);
        int bi = lane & 15;
        int brow = wn + (bi & 7);
        int bcol = ((bi >> 3) & 1) * 16;
        #pragma unroll
        for (int nt = 0; nt < 7; nt++)
            boff[nt] = SWZ((brow + nt * 8) * 128 + bcol);
    }

    float acc[2][7][4];
    #pragma unroll
    for (int mt = 0; mt < 2; mt++)
        #pragma unroll
        for (int nt = 0; nt < 7; nt++)
            #pragma unroll
            for (int i = 0; i < 4; i++) acc[mt][nt][i] = 0.f;

    auto load_stage = [&](int it) {
        const int stg = it % NSTG;
        const uint32_t sb = smb + stg * STG_SZ;
        const int kc = kbase + it * KC;
        #pragma unroll
        for (int q = tid; q < 1024; q += 256) {
            int r = q >> 3, c = q & 7;
            uint32_t so = SWZ(r * 128 + c * 16);
            size_t go = (size_t)(m0 + r) * KDIM + kc + c * 8;
            cpa16(sb + OFF_AH + so, Ahi + go);
            cpa16(sb + OFF_AL + so, Alo + go);
        }
        #pragma unroll
        for (int q = tid; q < 896; q += 256) {
            int r = q >> 3, c = q & 7;
            uint32_t so = SWZ(r * 128 + c * 16);
            size_t go = (size_t)(n0 + r) * KDIM + kc + c * 8;
            cpa16(sb + OFF_BH + so, Bhi + go);
            cpa16(sb + OFF_BL + so, Blo + go);
        }
    };

    load_stage(0);
    asm volatile("cp.async.commit_group;" ::: "memory");
    load_stage(1);
    asm volatile("cp.async.commit_group;" ::: "memory");

    for (int c = 0; c < NCHH; ++c) {
        asm volatile("cp.async.wait_group 1;" ::: "memory");
        __syncthreads();

        if (c + 2 < NCHH) load_stage(c + 2);
        asm volatile("cp.async.commit_group;" ::: "memory");

        const uint32_t sb = smb + (c % NSTG) * STG_SZ;
        #pragma unroll
        for (int kk = 0; kk < 4; kk++) {
            const uint32_t kd = kk * 32;
            uint32_t ah[2][4], al[2][4], bh[7][2], bl[7][2];
            #pragma unroll
            for (int mt = 0; mt < 2; mt++) {
                ldsm4(ah[mt], sb + OFF_AH + (aoff[mt] ^ kd));
                ldsm4(al[mt], sb + OFF_AL + (aoff[mt] ^ kd));
            }
            #pragma unroll
            for (int nt = 0; nt < 7; nt++) {
                ldsm2(bh[nt], sb + OFF_BH + (boff[nt] ^ kd));
                ldsm2(bl[nt], sb + OFF_BL + (boff[nt] ^ kd));
            }
            #pragma unroll
            for (int mt = 0; mt < 2; mt++)
                #pragma unroll
                for (int nt = 0; nt < 7; nt++) {
                    mma16816(acc[mt][nt], ah[mt], bh[nt]);
                    mma16816(acc[mt][nt], ah[mt], bl[nt]);
                    mma16816(acc[mt][nt], al[mt], bh[nt]);
                }
        }
    }

    const int l4 = lane >> 2;
    const int l2 = (lane & 3) * 2;
    float* mdst = g_m[ksl] + (size_t)pos * MSTRIDE;
    #pragma unroll
    for (int mt = 0; mt < 2; mt++) {
        int ocA = m0 + wm + mt * 16 + l4;
        int ocB = ocA + 8;
        #pragma unroll
        for (int nt = 0; nt < 7; nt++) {
            int col = n0 + wn + nt * 8 + l2;
            float2 vA, vB;
            vA.x = acc[mt][nt][0]; vA.y = acc[mt][nt][1];
            vB.x = acc[mt][nt][2]; vB.y = acc[mt][nt][3];
            *(float2*)(mdst + (size_t)ocA * NTP + col) = vA;
            *(float2*)(mdst + (size_t)ocB * NTP + col) = vB;
        }
    }
}

// ------------------- inverse transform: y = A^T m A + bias, relu -----------
__global__ __launch_bounds__(256) void itrans_kernel(const float* __restrict__ CB) {
    int t = blockIdx.x * blockDim.x + threadIdx.x;
    if (t >= 2048 * NTIL) return;
    int oc = t / NTIL;
    int tile = t - oc * NTIL;
    int ti = tile / NT14, tj = tile - ti * NT14;

    float m[16];
    #pragma unroll
    for (int p = 0; p < 16; p++) {
        size_t off = (size_t)p * MSTRIDE + (size_t)oc * NTP + tile;
        m[p] = g_m[0][off] + g_m[1][off];
    }

    float T0[4], T1[4];
    #pragma unroll
    for (int j = 0; j < 4; j++) {
        T0[j] = m[j] + m[4 + j] + m[8 + j];
        T1[j] = m[4 + j] - m[8 + j] - m[12 + j];
    }
    float y00 = T0[0] + T0[1] + T0[2];
    float y01 = T0[1] - T0[2] - T0[3];
    float y10 = T1[0] + T1[1] + T1[2];
    float y11 = T1[1] - T1[2] - T1[3];

    float bias = __ldg(&CB[oc]);
    float* hp = g_h + (size_t)oc * NPIX;
    int oy = 2 * ti, ox = 2 * tj;
    hp[oy * 28 + ox]           = fmaxf(y00 + bias, 0.f);
    hp[oy * 28 + ox + 1]       = fmaxf(y01 + bias, 0.f);
    hp[(oy + 1) * 28 + ox]     = fmaxf(y10 + bias, 0.f);
    hp[(oy + 1) * 28 + ox + 1] = fmaxf(y11 + bias, 0.f);
}

// --------------------- transpose g_h[ch][pix] -> g_ht[pix][ch] -------------
__global__ void transpose_kernel() {
    __shared__ float ts[32][33];
    int cb = blockIdx.x * 32;
    int pb = blockIdx.y * 32;
    int tx = threadIdx.x, ty = threadIdx.y;
    #pragma unroll
    for (int j = 0; j < 4; j++) {
        int ch = cb + ty + j * 8;
        int p = pb + tx;
        if (p < NPIX) ts[ty + j * 8][tx] = g_h[(size_t)ch * NPIX + p];
    }
    __syncthreads();
    #pragma unroll
    for (int j = 0; j < 4; j++) {
        int p = pb + ty + j * 8;
        int ch = cb + tx;
        if (p < NPIX) g_ht[(size_t)p * 2048 + ch] = ts[tx][ty + j * 8];
    }
}

// ------------------------------- heads -------------------------------------
__global__ __launch_bounds__(256) void heads_kernel(
    const float* __restrict__ reg_w, const float* __restrict__ reg_b,
    const float* __restrict__ cls_w, const float* __restrict__ cls_b)
{
    const int lane = threadIdx.x & 31;
    const int warp = threadIdx.x >> 5;
    const int p = blockIdx.x * 8 + warp;

    float4 hv[16];
    #pragma unroll
    for (int j = 0; j < 16; j++)
        hv[j] = __ldg((const float4*)(g_ht + (size_t)p * 2048 + lane * 4 + 128 * j));

    #pragma unroll 1
    for (int o = 0; o < 45; o++) {
        const float* w = (o < 36) ? (reg_w + o * 2048) : (cls_w + (o - 36) * 2048);
        float s = 0.f;
        #pragma unroll
        for (int j = 0; j < 16; j++) {
            float4 wq = __ldg((const float4*)(w + lane * 4 + 128 * j));
            s += hv[j].x * wq.x + hv[j].y * wq.y + hv[j].z * wq.z + hv[j].w * wq.w;
        }
        #pragma unroll
        for (int off = 16; off > 0; off >>= 1) s += __shfl_xor_sync(0xffffffffu, s, off);
        if (lane == 0) {
            float b = (o < 36) ? __ldg(&reg_b[o]) : __ldg(&cls_b[o - 36]);
            g_head[o * NPIX + p] = 1.f / (1.f + expf(-(s + b)));
        }
    }
}

// ------------------------- scan + gather (fused) ---------------------------
__device__ __forceinline__ bool anchor_valid(int j) {
    int a = j % 9, p = j / 9;
    int y = p / 28, x = p % 28;
    double scale = (a / 3 == 0) ? 64.0 : (a / 3 == 1) ? 128.0 : 256.0;
    double ratio = (a % 3 == 0) ? 0.5 : (a % 3 == 1) ? 1.0 : 2.0;
    double hh = scale / sqrt(ratio) / 448.0;
    double ww = scale * sqrt(ratio) / 448.0;
    double cy = ((double)y + 0.5) / 28.0;
    double cx = ((double)x + 0.5) / 28.0;
    double y1 = cy - hh / 2.0, x1 = cx - ww / 2.0;
    double y2 = cy + hh / 2.0, x2 = cx + ww / 2.0;
    return (y1 > 0.0) && (x1 > 0.0) && (y2 < 28.0) && (x2 < 28.0);
}

__global__ void scan_gather_kernel(float* __restrict__ out) {
    __shared__ int s[1024];
    const int tid = threadIdx.x;
    const int base = tid * 7;
    int f[7];
    int cnt = 0;
    #pragma unroll
    for (int i = 0; i < 7; i++) {
        int j = base + i;
        f[i] = (j < 7056 && anchor_valid(j)) ? 1 : 0;
        cnt += f[i];
    }
    s[tid] = cnt;
    __syncthreads();
    for (int off = 1; off < 1024; off <<= 1) {
        int v = s[tid];
        int add = (tid >= off) ? s[tid - off] : 0;
        __syncthreads();
        s[tid] = v + add;
        __syncthreads();
    }
    int pos = s[tid] - cnt;
    #pragma unroll
    for (int i = 0; i < 7; i++) {
        int j = base + i;
        if (j < 7056 && f[i]) {
            int a = j / NPIX, p = j % NPIX;
            float cls = g_head[(36 + a) * NPIX + p];
            float k = (cls > 0.9f) ? 1.f : 0.f;
            #pragma unroll
            for (int c = 0; c < 4; c++)
                out[pos * 4 + c] = g_head[(c * 9 + a) * NPIX + p] * k;
            pos++;
        }
    }
}

// ---------------------------------------------------------------------------
extern "C" void kernel_launch(void* const* d_in, const int* in_sizes, int n_in,
                              void* d_out, int out_size)
{
    const float* x      = (const float*)d_in[0];
    const float* conv_w = (const float*)d_in[1];
    const float* conv_b = (const float*)d_in[2];
    const float* reg_w  = (const float*)d_in[3];
    const float* reg_b  = (const float*)d_in[4];
    const float* cls_w  = (const float*)d_in[5];
    const float* cls_b  = (const float*)d_in[6];
    float* out = (float*)d_out;

    cudaFuncSetAttribute(wino_mma_kernel,
                         cudaFuncAttributeMaxDynamicSharedMemorySize, CONV_SMEM);

    wtrans_kernel<<<(2048 * 2048 / 4 + 255) / 256, 256>>>(conv_w);
    xtrans_kernel<<<(NTP * 2048 / 4 + 255) / 256, 256>>>(x);
    wino_mma_kernel<<<dim3(2, 16, 32), 256, CONV_SMEM>>>();
    itrans_kernel<<<(2048 * NTIL + 255) / 256, 256>>>(conv_b);
    transpose_kernel<<<dim3(64, 25), dim3(32, 8)>>>();
    heads_kernel<<<98, 256>>>(reg_w, reg_b, cls_w, cls_b);
    scan_gather_kernel<<<1, 1024>>>(out);
}